// round 2
// baseline (speedup 1.0000x reference)
#include <cuda_runtime.h>
#include <cstdint>

#define H 64
#define NN 100000
#define NE 1600000
#define WARPS 8
#define EPT 8   // edges (or nodes) per warp-tile

// scratch for segment sum (device global: no allocation allowed)
__device__ float g_mi[(size_t)NN * H];

// shared layout (floats):
//   sW1t : 64*132 = 8448   (transposed, padded: W1t[c*132+k])
//   sW2t : 64*68  = 4352   (W2t[c*68+k])
//   aux  : 4*64   = 256
//   sIn  : 8*1024 = 8192   (per-warp input staging, 8x128 each)
//   sT   : 8*512  = 4096   (per-warp hidden staging, 8x64 each)
#define SMEM_FLOATS (8448 + 4352 + 256 + 8192 + 4096)
#define SMEM_BYTES  (SMEM_FLOATS * 4)

__device__ __forceinline__ float fast_sigmoid(float z) {
    return 1.0f / (1.0f + __expf(-z));
}

__global__ void __launch_bounds__(256, 2) edge_kernel(
    const float* __restrict__ h, const float* __restrict__ x,
    const int* __restrict__ edge_index,           // int32! (JAX x64 disabled)
    const float* __restrict__ We1, const float* __restrict__ be1,
    const float* __restrict__ We2, const float* __restrict__ be2,
    const float* __restrict__ Winf, const float* __restrict__ binf)
{
    extern __shared__ float smem[];
    float* sW1 = smem;                  // [64][132] transposed
    float* sW2 = sW1 + 64 * 132;        // [64][68]  transposed
    float* sWinf = sW2 + 64 * 68;
    float* sB1 = sWinf + 64;
    float* sB2 = sB1 + 64;
    float* sDis = sB2 + 64;             // 8 warps * 8 edges
    float* sIn = sDis + 64;             // 8 * 1024
    float* sT  = sIn + 8 * 1024;        // 8 * 512

    const int tid = threadIdx.x;
    for (int i = tid; i < 128 * 64; i += 256) {
        int k = i >> 6, c = i & 63;
        sW1[c * 132 + k] = We1[i];
    }
    for (int i = tid; i < 64 * 64; i += 256) {
        int k = i >> 6, c = i & 63;
        sW2[c * 68 + k] = We2[i];
    }
    if (tid < 64) { sWinf[tid] = Winf[tid]; sB1[tid] = be1[tid]; sB2[tid] = be2[tid]; }
    __syncthreads();

    const int warp = tid >> 5, lane = tid & 31;
    const int c0 = lane, c1 = lane + 32;
    const float bi = binf[0];
    const float wf0 = sWinf[c0], wf1 = sWinf[c1];
    const float b1_0 = sB1[c0], b1_1 = sB1[c1];
    const float b2_0 = sB2[c0], b2_1 = sB2[c1];
    float* myIn = sIn + warp * 1024;
    float* myT  = sT  + warp * 512;
    float* myDis = sDis + warp * EPT;

    const int gw = blockIdx.x * WARPS + warp;
    const int nwarps = gridDim.x * WARPS;

    for (int base = gw * EPT; base < NE; base += nwarps * EPT) {
        int dst8[EPT], src8[EPT];
#pragma unroll
        for (int e = 0; e < EPT; e++) {
            src8[e] = edge_index[base + e];
            dst8[e] = edge_index[NE + base + e];
        }
        // stage e_in = [h[dst], h[src]]  (coalesced float2)
#pragma unroll
        for (int e = 0; e < EPT; e++) {
            const float* hd = h + (size_t)dst8[e] * H;
            const float* hs = h + (size_t)src8[e] * H;
            *reinterpret_cast<float2*>(myIn + e * 128 + 2 * lane) =
                *reinterpret_cast<const float2*>(hd + 2 * lane);
            *reinterpret_cast<float2*>(myIn + e * 128 + 64 + 2 * lane) =
                *reinterpret_cast<const float2*>(hs + 2 * lane);
        }
        if (lane < EPT) {
            int d = dst8[lane], s = src8[lane];
            float dx = x[d * 3 + 0] - x[s * 3 + 0];
            float dy = x[d * 3 + 1] - x[s * 3 + 1];
            float dz = x[d * 3 + 2] - x[s * 3 + 2];
            float dd = dx * dx + dy * dy + dz * dz;
            myDis[lane] = fast_sigmoid(30.0f / (sqrtf(dd) + 1e-8f));
        }
        __syncwarp();

        // layer 1: [8x128] @ [128x64]
        float a0[EPT], a1[EPT];
#pragma unroll
        for (int e = 0; e < EPT; e++) { a0[e] = b1_0; a1[e] = b1_1; }
#pragma unroll 2
        for (int k = 0; k < 128; k += 4) {
            float4 w0 = *reinterpret_cast<const float4*>(sW1 + c0 * 132 + k);
            float4 w1 = *reinterpret_cast<const float4*>(sW1 + c1 * 132 + k);
#pragma unroll
            for (int e = 0; e < EPT; e++) {
                float4 v = *reinterpret_cast<const float4*>(myIn + e * 128 + k);
                a0[e] = fmaf(v.x, w0.x, a0[e]); a0[e] = fmaf(v.y, w0.y, a0[e]);
                a0[e] = fmaf(v.z, w0.z, a0[e]); a0[e] = fmaf(v.w, w0.w, a0[e]);
                a1[e] = fmaf(v.x, w1.x, a1[e]); a1[e] = fmaf(v.y, w1.y, a1[e]);
                a1[e] = fmaf(v.z, w1.z, a1[e]); a1[e] = fmaf(v.w, w1.w, a1[e]);
            }
        }
#pragma unroll
        for (int e = 0; e < EPT; e++) {
            myT[e * 64 + c0] = fmaxf(a0[e], 0.0f);
            myT[e * 64 + c1] = fmaxf(a1[e], 0.0f);
        }
        __syncwarp();

        // layer 2: [8x64] @ [64x64]
        float m0[EPT], m1[EPT];
#pragma unroll
        for (int e = 0; e < EPT; e++) { m0[e] = b2_0; m1[e] = b2_1; }
#pragma unroll 2
        for (int k = 0; k < 64; k += 4) {
            float4 w0 = *reinterpret_cast<const float4*>(sW2 + c0 * 68 + k);
            float4 w1 = *reinterpret_cast<const float4*>(sW2 + c1 * 68 + k);
#pragma unroll
            for (int e = 0; e < EPT; e++) {
                float4 v = *reinterpret_cast<const float4*>(myT + e * 64 + k);
                m0[e] = fmaf(v.x, w0.x, m0[e]); m0[e] = fmaf(v.y, w0.y, m0[e]);
                m0[e] = fmaf(v.z, w0.z, m0[e]); m0[e] = fmaf(v.w, w0.w, m0[e]);
                m1[e] = fmaf(v.x, w1.x, m1[e]); m1[e] = fmaf(v.y, w1.y, m1[e]);
                m1[e] = fmaf(v.z, w1.z, m1[e]); m1[e] = fmaf(v.w, w1.w, m1[e]);
            }
        }
        __syncwarp();

        // gate: eij = mij . Winf + binf; w = sigmoid(eij * edge_dis)
#pragma unroll
        for (int e = 0; e < EPT; e++) {
            m0[e] = fmaxf(m0[e], 0.0f);
            m1[e] = fmaxf(m1[e], 0.0f);
            float p = m0[e] * wf0 + m1[e] * wf1;
#pragma unroll
            for (int o = 16; o > 0; o >>= 1) p += __shfl_xor_sync(0xffffffffu, p, o);
            float wgt = fast_sigmoid((p + bi) * myDis[e]);
            myT[e * 64 + c0] = m0[e] * wgt;
            myT[e * 64 + c1] = m1[e] * wgt;
        }
        __syncwarp();

        // vectorized scatter-add: two edges per pass across half-warps
#pragma unroll
        for (int ee = 0; ee < EPT / 2; ee++) {
            int e = ee * 2 + (lane >> 4);
            int li = lane & 15;
            float4 v = *reinterpret_cast<const float4*>(myT + e * 64 + li * 4);
            float* p = g_mi + (size_t)dst8[e] * H + li * 4;
            asm volatile("red.global.add.v4.f32 [%0], {%1,%2,%3,%4};"
                         :: "l"(p), "f"(v.x), "f"(v.y), "f"(v.z), "f"(v.w)
                         : "memory");
        }
        __syncwarp();
    }
}

__global__ void __launch_bounds__(256, 2) node_kernel(
    const float* __restrict__ h,
    const float* __restrict__ Wn1, const float* __restrict__ bn1,
    const float* __restrict__ Wn2, const float* __restrict__ bn2,
    const float* __restrict__ lng, const float* __restrict__ lnb,
    float* __restrict__ out)
{
    extern __shared__ float smem[];
    float* sW1 = smem;
    float* sW2 = sW1 + 64 * 132;
    float* sB1 = sW2 + 64 * 68;
    float* sB2 = sB1 + 64;
    float* sG  = sB2 + 64;
    float* sB  = sG + 64;
    float* sIn = sB + 64;
    float* sT  = sIn + 8 * 1024;

    const int tid = threadIdx.x;
    for (int i = tid; i < 128 * 64; i += 256) {
        int k = i >> 6, c = i & 63;
        sW1[c * 132 + k] = Wn1[i];
    }
    for (int i = tid; i < 64 * 64; i += 256) {
        int k = i >> 6, c = i & 63;
        sW2[c * 68 + k] = Wn2[i];
    }
    if (tid < 64) { sB1[tid] = bn1[tid]; sB2[tid] = bn2[tid]; sG[tid] = lng[tid]; sB[tid] = lnb[tid]; }
    __syncthreads();

    const int warp = tid >> 5, lane = tid & 31;
    const int c0 = lane, c1 = lane + 32;
    const float b1_0 = sB1[c0], b1_1 = sB1[c1];
    const float b2_0 = sB2[c0], b2_1 = sB2[c1];
    const float g0 = sG[c0], g1 = sG[c1];
    const float bb0 = sB[c0], bb1 = sB[c1];
    float* myIn = sIn + warp * 1024;
    float* myT  = sT + warp * 512;

    const int gw = blockIdx.x * WARPS + warp;
    const int nwarps = gridDim.x * WARPS;

    for (int base = gw * EPT; base < NN; base += nwarps * EPT) {
        // stage n_in = [mi, h]
#pragma unroll
        for (int e = 0; e < EPT; e++) {
            const float* mip = g_mi + (size_t)(base + e) * H;
            const float* hp  = h + (size_t)(base + e) * H;
            *reinterpret_cast<float2*>(myIn + e * 128 + 2 * lane) =
                *reinterpret_cast<const float2*>(mip + 2 * lane);
            *reinterpret_cast<float2*>(myIn + e * 128 + 64 + 2 * lane) =
                *reinterpret_cast<const float2*>(hp + 2 * lane);
        }
        __syncwarp();

        float a0[EPT], a1[EPT];
#pragma unroll
        for (int e = 0; e < EPT; e++) { a0[e] = b1_0; a1[e] = b1_1; }
#pragma unroll 2
        for (int k = 0; k < 128; k += 4) {
            float4 w0 = *reinterpret_cast<const float4*>(sW1 + c0 * 132 + k);
            float4 w1 = *reinterpret_cast<const float4*>(sW1 + c1 * 132 + k);
#pragma unroll
            for (int e = 0; e < EPT; e++) {
                float4 v = *reinterpret_cast<const float4*>(myIn + e * 128 + k);
                a0[e] = fmaf(v.x, w0.x, a0[e]); a0[e] = fmaf(v.y, w0.y, a0[e]);
                a0[e] = fmaf(v.z, w0.z, a0[e]); a0[e] = fmaf(v.w, w0.w, a0[e]);
                a1[e] = fmaf(v.x, w1.x, a1[e]); a1[e] = fmaf(v.y, w1.y, a1[e]);
                a1[e] = fmaf(v.z, w1.z, a1[e]); a1[e] = fmaf(v.w, w1.w, a1[e]);
            }
        }
#pragma unroll
        for (int e = 0; e < EPT; e++) {
            myT[e * 64 + c0] = fmaxf(a0[e], 0.0f);
            myT[e * 64 + c1] = fmaxf(a1[e], 0.0f);
        }
        __syncwarp();

        float u0[EPT], u1[EPT];
#pragma unroll
        for (int e = 0; e < EPT; e++) { u0[e] = b2_0; u1[e] = b2_1; }
#pragma unroll 2
        for (int k = 0; k < 64; k += 4) {
            float4 w0 = *reinterpret_cast<const float4*>(sW2 + c0 * 68 + k);
            float4 w1 = *reinterpret_cast<const float4*>(sW2 + c1 * 68 + k);
#pragma unroll
            for (int e = 0; e < EPT; e++) {
                float4 v = *reinterpret_cast<const float4*>(myT + e * 64 + k);
                u0[e] = fmaf(v.x, w0.x, u0[e]); u0[e] = fmaf(v.y, w0.y, u0[e]);
                u0[e] = fmaf(v.z, w0.z, u0[e]); u0[e] = fmaf(v.w, w0.w, u0[e]);
                u1[e] = fmaf(v.x, w1.x, u1[e]); u1[e] = fmaf(v.y, w1.y, u1[e]);
                u1[e] = fmaf(v.z, w1.z, u1[e]); u1[e] = fmaf(v.w, w1.w, u1[e]);
            }
        }

        // residual + layernorm, write out
#pragma unroll
        for (int e = 0; e < EPT; e++) {
            float z0 = u0[e] + myIn[e * 128 + 64 + c0];   // h still staged
            float z1 = u1[e] + myIn[e * 128 + 64 + c1];
            float s = z0 + z1;
            float q = z0 * z0 + z1 * z1;
#pragma unroll
            for (int o = 16; o > 0; o >>= 1) {
                s += __shfl_xor_sync(0xffffffffu, s, o);
                q += __shfl_xor_sync(0xffffffffu, q, o);
            }
            float mean = s * (1.0f / 64.0f);
            float var = q * (1.0f / 64.0f) - mean * mean;
            float inv = rsqrtf(var + 1e-5f);
            size_t ro = (size_t)(base + e) * H;
            out[ro + c0] = (z0 - mean) * inv * g0 + bb0;
            out[ro + c1] = (z1 - mean) * inv * g1 + bb1;
        }
        __syncwarp();
    }
}

__global__ void copy_x_kernel(const float4* __restrict__ x, float4* __restrict__ out)
{
    int i = blockIdx.x * blockDim.x + threadIdx.x;
    if (i < (NN * 3) / 4) out[i] = x[i];
}

extern "C" void kernel_launch(void* const* d_in, const int* in_sizes, int n_in,
                              void* d_out, int out_size)
{
    const float* h    = (const float*)d_in[0];
    const float* x    = (const float*)d_in[1];
    const int*   ei   = (const int*)d_in[2];     // int32 (JAX default x64 off)
    const float* We1  = (const float*)d_in[3];
    const float* be1  = (const float*)d_in[4];
    const float* We2  = (const float*)d_in[5];
    const float* be2  = (const float*)d_in[6];
    const float* Winf = (const float*)d_in[7];
    const float* binf = (const float*)d_in[8];
    const float* Wn1  = (const float*)d_in[9];
    const float* bn1  = (const float*)d_in[10];
    const float* Wn2  = (const float*)d_in[11];
    const float* bn2  = (const float*)d_in[12];
    const float* lng  = (const float*)d_in[13];
    const float* lnb  = (const float*)d_in[14];
    float* out = (float*)d_out;

    void* mi_ptr = nullptr;
    cudaGetSymbolAddress(&mi_ptr, g_mi);
    cudaMemsetAsync(mi_ptr, 0, sizeof(float) * (size_t)NN * H, 0);

    cudaFuncSetAttribute(edge_kernel, cudaFuncAttributeMaxDynamicSharedMemorySize, SMEM_BYTES);
    cudaFuncSetAttribute(node_kernel, cudaFuncAttributeMaxDynamicSharedMemorySize, SMEM_BYTES);

    edge_kernel<<<296, 256, SMEM_BYTES>>>(h, x, ei, We1, be1, We2, be2, Winf, binf);
    node_kernel<<<296, 256, SMEM_BYTES>>>(h, Wn1, bn1, Wn2, bn2, lng, lnb, out);

    // x pass-through, guarded by actual out_size
    if (out_size >= NN * H + NN * 3) {
        copy_x_kernel<<<(NN * 3 / 4 + 255) / 256, 256>>>((const float4*)x,
                                                         (float4*)(out + (size_t)NN * H));
    }
}

// round 3
// speedup vs baseline: 1.3980x; 1.3980x over previous
#include <cuda_runtime.h>
#include <cstdint>

#define H 64
#define NN 100000
#define NE 1600000

// scratch for segment sum (device global: no allocation allowed)
__device__ float g_mi[(size_t)NN * H];

__device__ __forceinline__ float fast_sigmoid(float z) {
    return 1.0f / (1.0f + __expf(-z));
}
__device__ __forceinline__ unsigned f2tf(float f) {
    unsigned u; asm("cvt.rna.tf32.f32 %0, %1;" : "=r"(u) : "f"(f)); return u;
}
__device__ __forceinline__ void mma_tf32(float c[4], const unsigned a[4], const unsigned b[2]) {
    asm volatile("mma.sync.aligned.m16n8k8.row.col.f32.tf32.tf32.f32 "
        "{%0,%1,%2,%3}, {%4,%5,%6,%7}, {%8,%9}, {%0,%1,%2,%3};"
        : "+f"(c[0]), "+f"(c[1]), "+f"(c[2]), "+f"(c[3])
        : "r"(a[0]), "r"(a[1]), "r"(a[2]), "r"(a[3]), "r"(b[0]), "r"(b[1]));
}

// ---------------------------------------------------------------------------
// Edge kernel: tf32 MMA, weights in registers, 64 edges per block-tile
// ---------------------------------------------------------------------------
#define TILE_E 64
#define PAD_A 132   // 132 % 32 == 4 -> conflict-free frag loads
#define PAD_H 68    // 68 % 32 == 4  -> conflict-free frag loads
// smem: sA 64*132 f, sH 64*68 f, sDis/sE/sWgt 64 f each, sDst 64 int
#define EK_SMEM_BYTES ((64*PAD_A + 64*PAD_H + 64*3 + 64) * 4)

__global__ void __launch_bounds__(256) edge_mma_kernel(
    const float* __restrict__ h, const float* __restrict__ x,
    const int* __restrict__ edge_index,
    const float* __restrict__ We1, const float* __restrict__ be1,
    const float* __restrict__ We2, const float* __restrict__ be2,
    const float* __restrict__ Winf, const float* __restrict__ binf)
{
    extern __shared__ float sm[];
    float* sA   = sm;                   // [64][132] (tf32 bits as float)
    float* sH   = sA + 64 * PAD_A;      // [64][68]
    float* sDis = sH + 64 * PAD_H;      // [64]
    float* sE   = sDis + 64;            // [64]
    float* sWgt = sE + 64;              // [64]
    int*   sDst = (int*)(sWgt + 64);    // [64]

    const int tid  = threadIdx.x;
    const int warp = tid >> 5, lane = tid & 31;
    const int lane4 = lane & 3, laned4 = lane >> 2;
    const int wm = warp & 1;       // row-half: rows 32*wm .. +32
    const int wn = warp >> 1;      // col-slice: cols 16*wn .. +16

    // ---- preload weights into registers (tf32), once per block ----
    unsigned wb1[16][2][2];
#pragma unroll
    for (int kt = 0; kt < 16; kt++)
#pragma unroll
        for (int nt = 0; nt < 2; nt++) {
            int k = kt * 8 + lane4;
            int n = wn * 16 + nt * 8 + laned4;
            wb1[kt][nt][0] = f2tf(We1[k * 64 + n]);
            wb1[kt][nt][1] = f2tf(We1[(k + 4) * 64 + n]);
        }
    unsigned wb2[8][2][2];
#pragma unroll
    for (int kt = 0; kt < 8; kt++)
#pragma unroll
        for (int nt = 0; nt < 2; nt++) {
            int k = kt * 8 + lane4;
            int n = wn * 16 + nt * 8 + laned4;
            wb2[kt][nt][0] = f2tf(We2[k * 64 + n]);
            wb2[kt][nt][1] = f2tf(We2[(k + 4) * 64 + n]);
        }
    float bias1[2][2], bias2[2][2], wf[2][2];
#pragma unroll
    for (int nt = 0; nt < 2; nt++) {
        int c = wn * 16 + nt * 8 + 2 * lane4;
        bias1[nt][0] = be1[c]; bias1[nt][1] = be1[c + 1];
        bias2[nt][0] = be2[c]; bias2[nt][1] = be2[c + 1];
        wf[nt][0]    = Winf[c]; wf[nt][1]   = Winf[c + 1];
    }
    const float binf0 = binf[0];

    const int se = tid >> 2;   // staging: edge id 0..63
    const int sp = tid & 3;    // staging: quarter 0..3

    const int ntiles = NE / TILE_E;
    for (int t = blockIdx.x; t < ntiles; t += gridDim.x) {
        const int base = t * TILE_E;
        __syncthreads();   // previous tile fully consumed (sA frag reads, sH scatter)

        // ---- stage per-edge scalars ----
        if (tid < 64) {
            int s = edge_index[base + tid];
            int d = edge_index[NE + base + tid];
            sDst[tid] = d;
            float dx = x[d * 3 + 0] - x[s * 3 + 0];
            float dy = x[d * 3 + 1] - x[s * 3 + 1];
            float dz = x[d * 3 + 2] - x[s * 3 + 2];
            float dd = dx * dx + dy * dy + dz * dz;
            sDis[tid] = fast_sigmoid(30.0f / (sqrtf(dd) + 1e-8f));
            sE[tid] = binf0;
        }
        // ---- stage sA = tf32([h[dst] | h[src]]), 4 threads per edge ----
        {
            int s = edge_index[base + se];
            int d = edge_index[NE + base + se];
            const float* srcp = (sp < 2) ? (h + (size_t)d * H) : (h + (size_t)s * H);
            int off = (sp & 1) * 32;
            float* dstp = sA + se * PAD_A + (sp >> 1) * 64 + off;
#pragma unroll
            for (int j = 0; j < 8; j++) {
                float4 v = *reinterpret_cast<const float4*>(srcp + off + j * 4);
                uint4 u;
                u.x = f2tf(v.x); u.y = f2tf(v.y); u.z = f2tf(v.z); u.w = f2tf(v.w);
                *reinterpret_cast<uint4*>(dstp + j * 4) = u;
            }
        }
        __syncthreads();

        // ---- GEMM1: [64x128] @ [128x64] ----
        float acc[2][2][4];
#pragma unroll
        for (int mt = 0; mt < 2; mt++)
#pragma unroll
            for (int nt = 0; nt < 2; nt++) {
                acc[mt][nt][0] = bias1[nt][0]; acc[mt][nt][1] = bias1[nt][1];
                acc[mt][nt][2] = bias1[nt][0]; acc[mt][nt][3] = bias1[nt][1];
            }
#pragma unroll
        for (int kt = 0; kt < 16; kt++) {
#pragma unroll
            for (int mt = 0; mt < 2; mt++) {
                int r = wm * 32 + mt * 16 + laned4;
                int c = kt * 8 + lane4;
                unsigned a[4];
                a[0] = __float_as_uint(sA[r * PAD_A + c]);
                a[1] = __float_as_uint(sA[(r + 8) * PAD_A + c]);
                a[2] = __float_as_uint(sA[r * PAD_A + c + 4]);
                a[3] = __float_as_uint(sA[(r + 8) * PAD_A + c + 4]);
#pragma unroll
                for (int nt = 0; nt < 2; nt++)
                    mma_tf32(acc[mt][nt], a, wb1[kt][nt]);
            }
        }
        // relu -> sH (stored as tf32 bits, ready for GEMM2 A)
#pragma unroll
        for (int mt = 0; mt < 2; mt++) {
            int r = wm * 32 + mt * 16 + laned4;
#pragma unroll
            for (int nt = 0; nt < 2; nt++) {
                int c = wn * 16 + nt * 8 + 2 * lane4;
                sH[r * PAD_H + c]           = __uint_as_float(f2tf(fmaxf(acc[mt][nt][0], 0.0f)));
                sH[r * PAD_H + c + 1]       = __uint_as_float(f2tf(fmaxf(acc[mt][nt][1], 0.0f)));
                sH[(r + 8) * PAD_H + c]     = __uint_as_float(f2tf(fmaxf(acc[mt][nt][2], 0.0f)));
                sH[(r + 8) * PAD_H + c + 1] = __uint_as_float(f2tf(fmaxf(acc[mt][nt][3], 0.0f)));
            }
        }
        __syncthreads();

        // ---- GEMM2: [64x64] @ [64x64] ----
        float macc[2][2][4];
#pragma unroll
        for (int mt = 0; mt < 2; mt++)
#pragma unroll
            for (int nt = 0; nt < 2; nt++) {
                macc[mt][nt][0] = bias2[nt][0]; macc[mt][nt][1] = bias2[nt][1];
                macc[mt][nt][2] = bias2[nt][0]; macc[mt][nt][3] = bias2[nt][1];
            }
#pragma unroll
        for (int kt = 0; kt < 8; kt++) {
#pragma unroll
            for (int mt = 0; mt < 2; mt++) {
                int r = wm * 32 + mt * 16 + laned4;
                int c = kt * 8 + lane4;
                unsigned a[4];
                a[0] = __float_as_uint(sH[r * PAD_H + c]);
                a[1] = __float_as_uint(sH[(r + 8) * PAD_H + c]);
                a[2] = __float_as_uint(sH[r * PAD_H + c + 4]);
                a[3] = __float_as_uint(sH[(r + 8) * PAD_H + c + 4]);
#pragma unroll
                for (int nt = 0; nt < 2; nt++)
                    mma_tf32(macc[mt][nt], a, wb2[kt][nt]);
            }
        }

        // ---- relu (in regs) + gate partial: eij = mij . Winf ----
#pragma unroll
        for (int mt = 0; mt < 2; mt++) {
            int r = wm * 32 + mt * 16 + laned4;
            float plo = 0.0f, phi = 0.0f;
#pragma unroll
            for (int nt = 0; nt < 2; nt++) {
                macc[mt][nt][0] = fmaxf(macc[mt][nt][0], 0.0f);
                macc[mt][nt][1] = fmaxf(macc[mt][nt][1], 0.0f);
                macc[mt][nt][2] = fmaxf(macc[mt][nt][2], 0.0f);
                macc[mt][nt][3] = fmaxf(macc[mt][nt][3], 0.0f);
                plo += macc[mt][nt][0] * wf[nt][0] + macc[mt][nt][1] * wf[nt][1];
                phi += macc[mt][nt][2] * wf[nt][0] + macc[mt][nt][3] * wf[nt][1];
            }
            plo += __shfl_xor_sync(0xffffffffu, plo, 1);
            plo += __shfl_xor_sync(0xffffffffu, plo, 2);
            phi += __shfl_xor_sync(0xffffffffu, phi, 1);
            phi += __shfl_xor_sync(0xffffffffu, phi, 2);
            if (lane4 == 0) {
                atomicAdd(&sE[r], plo);
                atomicAdd(&sE[r + 8], phi);
            }
        }
        __syncthreads();
        if (tid < 64) sWgt[tid] = fast_sigmoid(sE[tid] * sDis[tid]);
        __syncthreads();

        // ---- scale by gate -> sH (fp32 now) ----
#pragma unroll
        for (int mt = 0; mt < 2; mt++) {
            int r = wm * 32 + mt * 16 + laned4;
            float wlo = sWgt[r], whi = sWgt[r + 8];
#pragma unroll
            for (int nt = 0; nt < 2; nt++) {
                int c = wn * 16 + nt * 8 + 2 * lane4;
                sH[r * PAD_H + c]           = macc[mt][nt][0] * wlo;
                sH[r * PAD_H + c + 1]       = macc[mt][nt][1] * wlo;
                sH[(r + 8) * PAD_H + c]     = macc[mt][nt][2] * whi;
                sH[(r + 8) * PAD_H + c + 1] = macc[mt][nt][3] * whi;
            }
        }
        __syncthreads();

        // ---- scatter-add into g_mi ----
#pragma unroll
        for (int i = 0; i < 4; i++) {
            int idx = tid + i * 256;          // 0..1023 = 64 edges * 16 float4
            int e = idx >> 4, q = idx & 15;
            float4 v = *reinterpret_cast<const float4*>(sH + e * PAD_H + q * 4);
            float* p = g_mi + (size_t)sDst[e] * H + q * 4;
            asm volatile("red.global.add.v4.f32 [%0], {%1,%2,%3,%4};"
                         :: "l"(p), "f"(v.x), "f"(v.y), "f"(v.z), "f"(v.w)
                         : "memory");
        }
    }
}

// ---------------------------------------------------------------------------
// Node kernel: unchanged FFMA design (small fraction of runtime)
// ---------------------------------------------------------------------------
#define WARPS 8
#define EPT 8
#define NK_SMEM_FLOATS (8448 + 4352 + 256 + 8192 + 4096)
#define NK_SMEM_BYTES  (NK_SMEM_FLOATS * 4)

__global__ void __launch_bounds__(256, 2) node_kernel(
    const float* __restrict__ h,
    const float* __restrict__ Wn1, const float* __restrict__ bn1,
    const float* __restrict__ Wn2, const float* __restrict__ bn2,
    const float* __restrict__ lng, const float* __restrict__ lnb,
    float* __restrict__ out)
{
    extern __shared__ float smem[];
    float* sW1 = smem;
    float* sW2 = sW1 + 64 * 132;
    float* sB1 = sW2 + 64 * 68;
    float* sB2 = sB1 + 64;
    float* sG  = sB2 + 64;
    float* sB  = sG + 64;
    float* sIn = sB + 64;
    float* sT  = sIn + 8 * 1024;

    const int tid = threadIdx.x;
    for (int i = tid; i < 128 * 64; i += 256) {
        int k = i >> 6, c = i & 63;
        sW1[c * 132 + k] = Wn1[i];
    }
    for (int i = tid; i < 64 * 64; i += 256) {
        int k = i >> 6, c = i & 63;
        sW2[c * 68 + k] = Wn2[i];
    }
    if (tid < 64) { sB1[tid] = bn1[tid]; sB2[tid] = bn2[tid]; sG[tid] = lng[tid]; sB[tid] = lnb[tid]; }
    __syncthreads();

    const int warp = tid >> 5, lane = tid & 31;
    const int c0 = lane, c1 = lane + 32;
    const float b1_0 = sB1[c0], b1_1 = sB1[c1];
    const float b2_0 = sB2[c0], b2_1 = sB2[c1];
    const float g0 = sG[c0], g1 = sG[c1];
    const float bb0 = sB[c0], bb1 = sB[c1];
    float* myIn = sIn + warp * 1024;
    float* myT  = sT + warp * 512;

    const int gw = blockIdx.x * WARPS + warp;
    const int nwarps = gridDim.x * WARPS;

    for (int base = gw * EPT; base < NN; base += nwarps * EPT) {
#pragma unroll
        for (int e = 0; e < EPT; e++) {
            const float* mip = g_mi + (size_t)(base + e) * H;
            const float* hp  = h + (size_t)(base + e) * H;
            *reinterpret_cast<float2*>(myIn + e * 128 + 2 * lane) =
                *reinterpret_cast<const float2*>(mip + 2 * lane);
            *reinterpret_cast<float2*>(myIn + e * 128 + 64 + 2 * lane) =
                *reinterpret_cast<const float2*>(hp + 2 * lane);
        }
        __syncwarp();

        float a0[EPT], a1[EPT];
#pragma unroll
        for (int e = 0; e < EPT; e++) { a0[e] = b1_0; a1[e] = b1_1; }
#pragma unroll 2
        for (int k = 0; k < 128; k += 4) {
            float4 w0 = *reinterpret_cast<const float4*>(sW1 + c0 * 132 + k);
            float4 w1 = *reinterpret_cast<const float4*>(sW1 + c1 * 132 + k);
#pragma unroll
            for (int e = 0; e < EPT; e++) {
                float4 v = *reinterpret_cast<const float4*>(myIn + e * 128 + k);
                a0[e] = fmaf(v.x, w0.x, a0[e]); a0[e] = fmaf(v.y, w0.y, a0[e]);
                a0[e] = fmaf(v.z, w0.z, a0[e]); a0[e] = fmaf(v.w, w0.w, a0[e]);
                a1[e] = fmaf(v.x, w1.x, a1[e]); a1[e] = fmaf(v.y, w1.y, a1[e]);
                a1[e] = fmaf(v.z, w1.z, a1[e]); a1[e] = fmaf(v.w, w1.w, a1[e]);
            }
        }
#pragma unroll
        for (int e = 0; e < EPT; e++) {
            myT[e * 64 + c0] = fmaxf(a0[e], 0.0f);
            myT[e * 64 + c1] = fmaxf(a1[e], 0.0f);
        }
        __syncwarp();

        float u0[EPT], u1[EPT];
#pragma unroll
        for (int e = 0; e < EPT; e++) { u0[e] = b2_0; u1[e] = b2_1; }
#pragma unroll 2
        for (int k = 0; k < 64; k += 4) {
            float4 w0 = *reinterpret_cast<const float4*>(sW2 + c0 * 68 + k);
            float4 w1 = *reinterpret_cast<const float4*>(sW2 + c1 * 68 + k);
#pragma unroll
            for (int e = 0; e < EPT; e++) {
                float4 v = *reinterpret_cast<const float4*>(myT + e * 64 + k);
                u0[e] = fmaf(v.x, w0.x, u0[e]); u0[e] = fmaf(v.y, w0.y, u0[e]);
                u0[e] = fmaf(v.z, w0.z, u0[e]); u0[e] = fmaf(v.w, w0.w, u0[e]);
                u1[e] = fmaf(v.x, w1.x, u1[e]); u1[e] = fmaf(v.y, w1.y, u1[e]);
                u1[e] = fmaf(v.z, w1.z, u1[e]); u1[e] = fmaf(v.w, w1.w, u1[e]);
            }
        }

#pragma unroll
        for (int e = 0; e < EPT; e++) {
            float z0 = u0[e] + myIn[e * 128 + 64 + c0];
            float z1 = u1[e] + myIn[e * 128 + 64 + c1];
            float s = z0 + z1;
            float q = z0 * z0 + z1 * z1;
#pragma unroll
            for (int o = 16; o > 0; o >>= 1) {
                s += __shfl_xor_sync(0xffffffffu, s, o);
                q += __shfl_xor_sync(0xffffffffu, q, o);
            }
            float mean = s * (1.0f / 64.0f);
            float var = q * (1.0f / 64.0f) - mean * mean;
            float inv = rsqrtf(var + 1e-5f);
            size_t ro = (size_t)(base + e) * H;
            out[ro + c0] = (z0 - mean) * inv * g0 + bb0;
            out[ro + c1] = (z1 - mean) * inv * g1 + bb1;
        }
        __syncwarp();
    }
}

__global__ void copy_x_kernel(const float4* __restrict__ x, float4* __restrict__ out)
{
    int i = blockIdx.x * blockDim.x + threadIdx.x;
    if (i < (NN * 3) / 4) out[i] = x[i];
}

extern "C" void kernel_launch(void* const* d_in, const int* in_sizes, int n_in,
                              void* d_out, int out_size)
{
    const float* h    = (const float*)d_in[0];
    const float* x    = (const float*)d_in[1];
    const int*   ei   = (const int*)d_in[2];
    const float* We1  = (const float*)d_in[3];
    const float* be1  = (const float*)d_in[4];
    const float* We2  = (const float*)d_in[5];
    const float* be2  = (const float*)d_in[6];
    const float* Winf = (const float*)d_in[7];
    const float* binf = (const float*)d_in[8];
    const float* Wn1  = (const float*)d_in[9];
    const float* bn1  = (const float*)d_in[10];
    const float* Wn2  = (const float*)d_in[11];
    const float* bn2  = (const float*)d_in[12];
    const float* lng  = (const float*)d_in[13];
    const float* lnb  = (const float*)d_in[14];
    float* out = (float*)d_out;

    void* mi_ptr = nullptr;
    cudaGetSymbolAddress(&mi_ptr, g_mi);
    cudaMemsetAsync(mi_ptr, 0, sizeof(float) * (size_t)NN * H, 0);

    cudaFuncSetAttribute(edge_mma_kernel, cudaFuncAttributeMaxDynamicSharedMemorySize, EK_SMEM_BYTES);
    cudaFuncSetAttribute(node_kernel, cudaFuncAttributeMaxDynamicSharedMemorySize, NK_SMEM_BYTES);

    edge_mma_kernel<<<296, 256, EK_SMEM_BYTES>>>(h, x, ei, We1, be1, We2, be2, Winf, binf);
    node_kernel<<<296, 256, NK_SMEM_BYTES>>>(h, Wn1, bn1, Wn2, bn2, lng, lnb, out);

    if (out_size >= NN * H + NN * 3) {
        copy_x_kernel<<<(NN * 3 / 4 + 255) / 256, 256>>>((const float4*)x,
                                                         (float4*)(out + (size_t)NN * H));
    }
}

// round 4
// speedup vs baseline: 1.6800x; 1.2017x over previous
#include <cuda_runtime.h>
#include <cstdint>

#define H 64
#define NN 100000
#define NE 1600000

// scratch for segment sum (device global: no allocation allowed)
__device__ float g_mi[(size_t)NN * H];

__device__ __forceinline__ float fast_sigmoid(float z) {
    return 1.0f / (1.0f + __expf(-z));
}
__device__ __forceinline__ unsigned f2tf(float f) {
    unsigned u; asm("cvt.rna.tf32.f32 %0, %1;" : "=r"(u) : "f"(f)); return u;
}
__device__ __forceinline__ void mma_tf32(float c[4], const unsigned a[4], const unsigned b[2]) {
    asm volatile("mma.sync.aligned.m16n8k8.row.col.f32.tf32.tf32.f32 "
        "{%0,%1,%2,%3}, {%4,%5,%6,%7}, {%8,%9}, {%0,%1,%2,%3};"
        : "+f"(c[0]), "+f"(c[1]), "+f"(c[2]), "+f"(c[3])
        : "r"(a[0]), "r"(a[1]), "r"(a[2]), "r"(a[3]), "r"(b[0]), "r"(b[1]));
}
__device__ __forceinline__ void ldmx4(unsigned a[4], unsigned saddr) {
    asm volatile("ldmatrix.sync.aligned.m8n8.x4.shared.b16 {%0,%1,%2,%3}, [%4];"
        : "=r"(a[0]), "=r"(a[1]), "=r"(a[2]), "=r"(a[3]) : "r"(saddr));
}
__device__ __forceinline__ void ldmx2(unsigned b[2], unsigned saddr) {
    asm volatile("ldmatrix.sync.aligned.m8n8.x2.shared.b16 {%0,%1}, [%2];"
        : "=r"(b[0]), "=r"(b[1]) : "r"(saddr));
}

// ---------------------------------------------------------------------------
// Edge kernel: tf32 MMA via ldmatrix, 64 edges/tile, 2 blocks/SM
// ---------------------------------------------------------------------------
#define TILE_E 64
#define PAD_A 132   // row stride (floats): r*132 % 32 = r*4 -> conflict-free ldmatrix
#define PAD_H 68    // r*68 % 32 = r*4 -> conflict-free
// smem floats: sA 64*132, sW1t 64*132, sH 64*68, sDis/sE/sWgt 64 each, sDst 64
#define EK_SMEM_FLOATS (64*PAD_A + 64*PAD_A + 64*PAD_H + 64*4)
#define EK_SMEM_BYTES  (EK_SMEM_FLOATS * 4)

__global__ void __launch_bounds__(256, 2) edge_mma_kernel(
    const float* __restrict__ h, const float* __restrict__ x,
    const int* __restrict__ edge_index,
    const float* __restrict__ We1, const float* __restrict__ be1,
    const float* __restrict__ We2, const float* __restrict__ be2,
    const float* __restrict__ Winf, const float* __restrict__ binf)
{
    extern __shared__ float sm[];
    float* sA   = sm;                     // [64][132] tf32 bits
    float* sW1t = sA + 64 * PAD_A;        // [64][132] W1 transposed [n][k], tf32 bits
    float* sH   = sW1t + 64 * PAD_A;      // [64][68]
    float* sDis = sH + 64 * PAD_H;        // [64]
    float* sE   = sDis + 64;              // [64]
    float* sWgt = sE + 64;                // [64]
    int*   sDst = (int*)(sWgt + 64);      // [64]

    const int tid  = threadIdx.x;
    const int warp = tid >> 5, lane = tid & 31;
    const int lane4 = lane & 3, laned4 = lane >> 2;
    const int wm = warp & 1;       // row-half: rows 32*wm .. +32
    const int wn = warp >> 1;      // col-slice: cols 16*wn .. +16

    // ---- stage W1 transposed into smem (once per block) ----
    for (int i = tid; i < 128 * 64; i += 256) {
        int k = i >> 6, n = i & 63;
        sW1t[n * PAD_A + k] = __uint_as_float(f2tf(We1[i]));
    }

    // ---- W2 slice in registers (tf32) ----
    unsigned wb2[8][2][2];
#pragma unroll
    for (int kt = 0; kt < 8; kt++)
#pragma unroll
        for (int nt = 0; nt < 2; nt++) {
            int k = kt * 8 + lane4;
            int n = wn * 16 + nt * 8 + laned4;
            wb2[kt][nt][0] = f2tf(We2[k * 64 + n]);
            wb2[kt][nt][1] = f2tf(We2[(k + 4) * 64 + n]);
        }
    float bias1[2][2], bias2[2][2], wf[2][2];
#pragma unroll
    for (int nt = 0; nt < 2; nt++) {
        int c = wn * 16 + nt * 8 + 2 * lane4;
        bias1[nt][0] = be1[c]; bias1[nt][1] = be1[c + 1];
        bias2[nt][0] = be2[c]; bias2[nt][1] = be2[c + 1];
        wf[nt][0]    = Winf[c]; wf[nt][1]   = Winf[c + 1];
    }
    const float binf0 = binf[0];

    // ---- ldmatrix per-lane base offsets ----
    const int sub = lane >> 3, r8 = lane & 7;
    const int aRow = (sub & 1) * 8 + r8;    // 0..15 within 16-row tile
    const int aCol = (sub >> 1) * 4;        // 0 or 4 (floats)
    unsigned sA_s  = (unsigned)__cvta_generic_to_shared(sA);
    unsigned sW1_s = (unsigned)__cvta_generic_to_shared(sW1t);
    unsigned sH_s  = (unsigned)__cvta_generic_to_shared(sH);
    const unsigned aoff1 = sA_s + ((wm * 32 + aRow) * PAD_A + aCol) * 4;
    const unsigned aoff2 = sH_s + ((wm * 32 + aRow) * PAD_H + aCol) * 4;
    const int bl = lane & 15;
    const unsigned boff1 = sW1_s + ((wn * 16 + (bl & 7)) * PAD_A + (bl >> 3) * 4) * 4;

    const int se = tid >> 2;   // staging: edge id 0..63
    const int sp = tid & 3;    // staging: quarter 0..3

    const int ntiles = NE / TILE_E;
    for (int t = blockIdx.x; t < ntiles; t += gridDim.x) {
        const int base = t * TILE_E;
        __syncthreads();   // prev tile: sA frag reads + sH scatter reads done

        // ---- stage per-edge scalars ----
        if (tid < 64) {
            int s = edge_index[base + tid];
            int d = edge_index[NE + base + tid];
            sDst[tid] = d;
            float dx = x[d * 3 + 0] - x[s * 3 + 0];
            float dy = x[d * 3 + 1] - x[s * 3 + 1];
            float dz = x[d * 3 + 2] - x[s * 3 + 2];
            float dd = dx * dx + dy * dy + dz * dz;
            sDis[tid] = fast_sigmoid(30.0f / (sqrtf(dd) + 1e-8f));
            sE[tid] = binf0;
        }
        // ---- stage sA = tf32([h[dst] | h[src]]), 4 threads per edge ----
        {
            int s = edge_index[base + se];
            int d = edge_index[NE + base + se];
            const float* srcp = (sp < 2) ? (h + (size_t)d * H) : (h + (size_t)s * H);
            int off = (sp & 1) * 32;
            float* dstp = sA + se * PAD_A + (sp >> 1) * 64 + off;
#pragma unroll
            for (int j = 0; j < 8; j++) {
                float4 v = *reinterpret_cast<const float4*>(srcp + off + j * 4);
                uint4 u;
                u.x = f2tf(v.x); u.y = f2tf(v.y); u.z = f2tf(v.z); u.w = f2tf(v.w);
                *reinterpret_cast<uint4*>(dstp + j * 4) = u;
            }
        }
        __syncthreads();

        // ---- GEMM1: [64x128] @ [128x64] ----
        float acc[2][2][4];
#pragma unroll
        for (int mt = 0; mt < 2; mt++)
#pragma unroll
            for (int nt = 0; nt < 2; nt++) {
                acc[mt][nt][0] = bias1[nt][0]; acc[mt][nt][1] = bias1[nt][1];
                acc[mt][nt][2] = bias1[nt][0]; acc[mt][nt][3] = bias1[nt][1];
            }
#pragma unroll
        for (int kt = 0; kt < 16; kt++) {
            unsigned bf0[2], bf1[2];
            ldmx2(bf0, boff1 + (kt * 8) * 4);
            ldmx2(bf1, boff1 + (8 * PAD_A + kt * 8) * 4);
#pragma unroll
            for (int mt = 0; mt < 2; mt++) {
                unsigned a[4];
                ldmx4(a, aoff1 + (mt * 16 * PAD_A + kt * 8) * 4);
                mma_tf32(acc[mt][0], a, bf0);
                mma_tf32(acc[mt][1], a, bf1);
            }
        }
        // relu -> sH (tf32 bits, A-operand for GEMM2)
#pragma unroll
        for (int mt = 0; mt < 2; mt++) {
            int r = wm * 32 + mt * 16 + laned4;
#pragma unroll
            for (int nt = 0; nt < 2; nt++) {
                int c = wn * 16 + nt * 8 + 2 * lane4;
                sH[r * PAD_H + c]           = __uint_as_float(f2tf(fmaxf(acc[mt][nt][0], 0.0f)));
                sH[r * PAD_H + c + 1]       = __uint_as_float(f2tf(fmaxf(acc[mt][nt][1], 0.0f)));
                sH[(r + 8) * PAD_H + c]     = __uint_as_float(f2tf(fmaxf(acc[mt][nt][2], 0.0f)));
                sH[(r + 8) * PAD_H + c + 1] = __uint_as_float(f2tf(fmaxf(acc[mt][nt][3], 0.0f)));
            }
        }
        __syncthreads();

        // ---- GEMM2: [64x64] @ [64x64] ----
        float macc[2][2][4];
#pragma unroll
        for (int mt = 0; mt < 2; mt++)
#pragma unroll
            for (int nt = 0; nt < 2; nt++) {
                macc[mt][nt][0] = bias2[nt][0]; macc[mt][nt][1] = bias2[nt][1];
                macc[mt][nt][2] = bias2[nt][0]; macc[mt][nt][3] = bias2[nt][1];
            }
#pragma unroll
        for (int kt = 0; kt < 8; kt++) {
#pragma unroll
            for (int mt = 0; mt < 2; mt++) {
                unsigned a[4];
                ldmx4(a, aoff2 + (mt * 16 * PAD_H + kt * 8) * 4);
                mma_tf32(macc[mt][0], a, wb2[kt][0]);
                mma_tf32(macc[mt][1], a, wb2[kt][1]);
            }
        }

        // ---- relu (regs) + gate partial: eij = mij . Winf ----
#pragma unroll
        for (int mt = 0; mt < 2; mt++) {
            int r = wm * 32 + mt * 16 + laned4;
            float plo = 0.0f, phi = 0.0f;
#pragma unroll
            for (int nt = 0; nt < 2; nt++) {
                macc[mt][nt][0] = fmaxf(macc[mt][nt][0], 0.0f);
                macc[mt][nt][1] = fmaxf(macc[mt][nt][1], 0.0f);
                macc[mt][nt][2] = fmaxf(macc[mt][nt][2], 0.0f);
                macc[mt][nt][3] = fmaxf(macc[mt][nt][3], 0.0f);
                plo += macc[mt][nt][0] * wf[nt][0] + macc[mt][nt][1] * wf[nt][1];
                phi += macc[mt][nt][2] * wf[nt][0] + macc[mt][nt][3] * wf[nt][1];
            }
            plo += __shfl_xor_sync(0xffffffffu, plo, 1);
            plo += __shfl_xor_sync(0xffffffffu, plo, 2);
            phi += __shfl_xor_sync(0xffffffffu, phi, 1);
            phi += __shfl_xor_sync(0xffffffffu, phi, 2);
            if (lane4 == 0) {
                atomicAdd(&sE[r], plo);
                atomicAdd(&sE[r + 8], phi);
            }
        }
        __syncthreads();   // all GEMM2 sH reads + sE atomics complete

        // gate weights (tid<64) and unscaled relu values -> sH, concurrently
        if (tid < 64) sWgt[tid] = fast_sigmoid(sE[tid] * sDis[tid]);
#pragma unroll
        for (int mt = 0; mt < 2; mt++) {
            int r = wm * 32 + mt * 16 + laned4;
#pragma unroll
            for (int nt = 0; nt < 2; nt++) {
                int c = wn * 16 + nt * 8 + 2 * lane4;
                sH[r * PAD_H + c]           = macc[mt][nt][0];
                sH[r * PAD_H + c + 1]       = macc[mt][nt][1];
                sH[(r + 8) * PAD_H + c]     = macc[mt][nt][2];
                sH[(r + 8) * PAD_H + c + 1] = macc[mt][nt][3];
            }
        }
        __syncthreads();

        // ---- scatter-add into g_mi (gate folded in) ----
#pragma unroll
        for (int i = 0; i < 4; i++) {
            int idx = tid + i * 256;          // 0..1023 = 64 edges * 16 float4
            int e = idx >> 4, q = idx & 15;
            float w = sWgt[e];
            float4 v = *reinterpret_cast<const float4*>(sH + e * PAD_H + q * 4);
            float* p = g_mi + (size_t)sDst[e] * H + q * 4;
            asm volatile("red.global.add.v4.f32 [%0], {%1,%2,%3,%4};"
                         :: "l"(p), "f"(v.x * w), "f"(v.y * w), "f"(v.z * w), "f"(v.w * w)
                         : "memory");
        }
    }
}

// ---------------------------------------------------------------------------
// Node kernel: unchanged FFMA design (small fraction of runtime)
// ---------------------------------------------------------------------------
#define WARPS 8
#define EPT 8
#define NK_SMEM_FLOATS (8448 + 4352 + 256 + 8192 + 4096)
#define NK_SMEM_BYTES  (NK_SMEM_FLOATS * 4)

__global__ void __launch_bounds__(256, 2) node_kernel(
    const float* __restrict__ h,
    const float* __restrict__ Wn1, const float* __restrict__ bn1,
    const float* __restrict__ Wn2, const float* __restrict__ bn2,
    const float* __restrict__ lng, const float* __restrict__ lnb,
    float* __restrict__ out)
{
    extern __shared__ float smem[];
    float* sW1 = smem;
    float* sW2 = sW1 + 64 * 132;
    float* sB1 = sW2 + 64 * 68;
    float* sB2 = sB1 + 64;
    float* sG  = sB2 + 64;
    float* sB  = sG + 64;
    float* sIn = sB + 64;
    float* sT  = sIn + 8 * 1024;

    const int tid = threadIdx.x;
    for (int i = tid; i < 128 * 64; i += 256) {
        int k = i >> 6, c = i & 63;
        sW1[c * 132 + k] = Wn1[i];
    }
    for (int i = tid; i < 64 * 64; i += 256) {
        int k = i >> 6, c = i & 63;
        sW2[c * 68 + k] = Wn2[i];
    }
    if (tid < 64) { sB1[tid] = bn1[tid]; sB2[tid] = bn2[tid]; sG[tid] = lng[tid]; sB[tid] = lnb[tid]; }
    __syncthreads();

    const int warp = tid >> 5, lane = tid & 31;
    const int c0 = lane, c1 = lane + 32;
    const float b1_0 = sB1[c0], b1_1 = sB1[c1];
    const float b2_0 = sB2[c0], b2_1 = sB2[c1];
    const float g0 = sG[c0], g1 = sG[c1];
    const float bb0 = sB[c0], bb1 = sB[c1];
    float* myIn = sIn + warp * 1024;
    float* myT  = sT + warp * 512;

    const int gw = blockIdx.x * WARPS + warp;
    const int nwarps = gridDim.x * WARPS;

    for (int base = gw * EPT; base < NN; base += nwarps * EPT) {
#pragma unroll
        for (int e = 0; e < EPT; e++) {
            const float* mip = g_mi + (size_t)(base + e) * H;
            const float* hp  = h + (size_t)(base + e) * H;
            *reinterpret_cast<float2*>(myIn + e * 128 + 2 * lane) =
                *reinterpret_cast<const float2*>(mip + 2 * lane);
            *reinterpret_cast<float2*>(myIn + e * 128 + 64 + 2 * lane) =
                *reinterpret_cast<const float2*>(hp + 2 * lane);
        }
        __syncwarp();

        float a0[EPT], a1[EPT];
#pragma unroll
        for (int e = 0; e < EPT; e++) { a0[e] = b1_0; a1[e] = b1_1; }
#pragma unroll 2
        for (int k = 0; k < 128; k += 4) {
            float4 w0 = *reinterpret_cast<const float4*>(sW1 + c0 * 132 + k);
            float4 w1 = *reinterpret_cast<const float4*>(sW1 + c1 * 132 + k);
#pragma unroll
            for (int e = 0; e < EPT; e++) {
                float4 v = *reinterpret_cast<const float4*>(myIn + e * 128 + k);
                a0[e] = fmaf(v.x, w0.x, a0[e]); a0[e] = fmaf(v.y, w0.y, a0[e]);
                a0[e] = fmaf(v.z, w0.z, a0[e]); a0[e] = fmaf(v.w, w0.w, a0[e]);
                a1[e] = fmaf(v.x, w1.x, a1[e]); a1[e] = fmaf(v.y, w1.y, a1[e]);
                a1[e] = fmaf(v.z, w1.z, a1[e]); a1[e] = fmaf(v.w, w1.w, a1[e]);
            }
        }
#pragma unroll
        for (int e = 0; e < EPT; e++) {
            myT[e * 64 + c0] = fmaxf(a0[e], 0.0f);
            myT[e * 64 + c1] = fmaxf(a1[e], 0.0f);
        }
        __syncwarp();

        float u0[EPT], u1[EPT];
#pragma unroll
        for (int e = 0; e < EPT; e++) { u0[e] = b2_0; u1[e] = b2_1; }
#pragma unroll 2
        for (int k = 0; k < 64; k += 4) {
            float4 w0 = *reinterpret_cast<const float4*>(sW2 + c0 * 68 + k);
            float4 w1 = *reinterpret_cast<const float4*>(sW2 + c1 * 68 + k);
#pragma unroll
            for (int e = 0; e < EPT; e++) {
                float4 v = *reinterpret_cast<const float4*>(myT + e * 64 + k);
                u0[e] = fmaf(v.x, w0.x, u0[e]); u0[e] = fmaf(v.y, w0.y, u0[e]);
                u0[e] = fmaf(v.z, w0.z, u0[e]); u0[e] = fmaf(v.w, w0.w, u0[e]);
                u1[e] = fmaf(v.x, w1.x, u1[e]); u1[e] = fmaf(v.y, w1.y, u1[e]);
                u1[e] = fmaf(v.z, w1.z, u1[e]); u1[e] = fmaf(v.w, w1.w, u1[e]);
            }
        }

#pragma unroll
        for (int e = 0; e < EPT; e++) {
            float z0 = u0[e] + myIn[e * 128 + 64 + c0];
            float z1 = u1[e] + myIn[e * 128 + 64 + c1];
            float s = z0 + z1;
            float q = z0 * z0 + z1 * z1;
#pragma unroll
            for (int o = 16; o > 0; o >>= 1) {
                s += __shfl_xor_sync(0xffffffffu, s, o);
                q += __shfl_xor_sync(0xffffffffu, q, o);
            }
            float mean = s * (1.0f / 64.0f);
            float var = q * (1.0f / 64.0f) - mean * mean;
            float inv = rsqrtf(var + 1e-5f);
            size_t ro = (size_t)(base + e) * H;
            out[ro + c0] = (z0 - mean) * inv * g0 + bb0;
            out[ro + c1] = (z1 - mean) * inv * g1 + bb1;
        }
        __syncwarp();
    }
}

__global__ void copy_x_kernel(const float4* __restrict__ x, float4* __restrict__ out)
{
    int i = blockIdx.x * blockDim.x + threadIdx.x;
    if (i < (NN * 3) / 4) out[i] = x[i];
}

extern "C" void kernel_launch(void* const* d_in, const int* in_sizes, int n_in,
                              void* d_out, int out_size)
{
    const float* h    = (const float*)d_in[0];
    const float* x    = (const float*)d_in[1];
    const int*   ei   = (const int*)d_in[2];
    const float* We1  = (const float*)d_in[3];
    const float* be1  = (const float*)d_in[4];
    const float* We2  = (const float*)d_in[5];
    const float* be2  = (const float*)d_in[6];
    const float* Winf = (const float*)d_in[7];
    const float* binf = (const float*)d_in[8];
    const float* Wn1  = (const float*)d_in[9];
    const float* bn1  = (const float*)d_in[10];
    const float* Wn2  = (const float*)d_in[11];
    const float* bn2  = (const float*)d_in[12];
    const float* lng  = (const float*)d_in[13];
    const float* lnb  = (const float*)d_in[14];
    float* out = (float*)d_out;

    void* mi_ptr = nullptr;
    cudaGetSymbolAddress(&mi_ptr, g_mi);
    cudaMemsetAsync(mi_ptr, 0, sizeof(float) * (size_t)NN * H, 0);

    cudaFuncSetAttribute(edge_mma_kernel, cudaFuncAttributeMaxDynamicSharedMemorySize, EK_SMEM_BYTES);
    cudaFuncSetAttribute(node_kernel, cudaFuncAttributeMaxDynamicSharedMemorySize, NK_SMEM_BYTES);

    edge_mma_kernel<<<296, 256, EK_SMEM_BYTES>>>(h, x, ei, We1, be1, We2, be2, Winf, binf);
    node_kernel<<<296, 256, NK_SMEM_BYTES>>>(h, Wn1, bn1, Wn2, bn2, lng, lnb, out);

    if (out_size >= NN * H + NN * 3) {
        copy_x_kernel<<<(NN * 3 / 4 + 255) / 256, 256>>>((const float4*)x,
                                                         (float4*)(out + (size_t)NN * H));
    }
}

// round 5
// speedup vs baseline: 2.1382x; 1.2727x over previous
#include <cuda_runtime.h>
#include <cuda_fp16.h>
#include <cstdint>

#define H 64
#define NN 100000
#define NE 1600000

// scratch for segment sum (device global: no allocation allowed)
__device__ float g_mi[(size_t)NN * H];

__device__ __forceinline__ float fast_sigmoid(float z) {
    return 1.0f / (1.0f + __expf(-z));
}
__device__ __forceinline__ void mma_f16(float c[4], const unsigned a[4], const unsigned b[2]) {
    asm volatile("mma.sync.aligned.m16n8k16.row.col.f32.f16.f16.f32 "
        "{%0,%1,%2,%3}, {%4,%5,%6,%7}, {%8,%9}, {%0,%1,%2,%3};"
        : "+f"(c[0]), "+f"(c[1]), "+f"(c[2]), "+f"(c[3])
        : "r"(a[0]), "r"(a[1]), "r"(a[2]), "r"(a[3]), "r"(b[0]), "r"(b[1]));
}
__device__ __forceinline__ void ldmx4(unsigned a[4], unsigned saddr) {
    asm volatile("ldmatrix.sync.aligned.m8n8.x4.shared.b16 {%0,%1,%2,%3}, [%4];"
        : "=r"(a[0]), "=r"(a[1]), "=r"(a[2]), "=r"(a[3]) : "r"(saddr));
}
__device__ __forceinline__ void ldmx2(unsigned b[2], unsigned saddr) {
    asm volatile("ldmatrix.sync.aligned.m8n8.x2.shared.b16 {%0,%1}, [%2];"
        : "=r"(b[0]), "=r"(b[1]) : "r"(saddr));
}
__device__ __forceinline__ unsigned h2u(half2 v) { return *reinterpret_cast<unsigned*>(&v); }

// ---------------------------------------------------------------------------
// Edge kernel: fp16 MMA (m16n8k16), 64 edges/tile, 2 blocks/SM
// ---------------------------------------------------------------------------
#define TILE_E 64
#define PAD_A2 136   // halfs per row: 272B, 272%128=16 -> conflict-free ldmatrix
#define PAD_H2 72    // halfs per row: 144B, 144%128=16 -> conflict-free
// smem: sA 64*136 h, sW1t 64*136 h, sH 64*72 h, sDis 64 f, sE 64 f, sDst 64 i
#define EK_SMEM_BYTES (64*PAD_A2*2 + 64*PAD_A2*2 + 64*PAD_H2*2 + 64*4*3)

__global__ void __launch_bounds__(256, 2) edge_mma_kernel(
    const float* __restrict__ h, const float* __restrict__ x,
    const int* __restrict__ edge_index,
    const float* __restrict__ We1, const float* __restrict__ be1,
    const float* __restrict__ We2, const float* __restrict__ be2,
    const float* __restrict__ Winf, const float* __restrict__ binf)
{
    extern __shared__ char smraw[];
    half*  sA   = (half*)smraw;                    // [64][136] fp16
    half*  sW1t = sA + 64 * PAD_A2;                // [64][136] W1^T [n][k] fp16
    half*  sH   = sW1t + 64 * PAD_A2;              // [64][72]  fp16
    float* sDis = (float*)(sH + 64 * PAD_H2);      // [64]
    float* sE   = sDis + 64;                       // [64]
    int*   sDst = (int*)(sE + 64);                 // [64]

    const int tid  = threadIdx.x;
    const int warp = tid >> 5, lane = tid & 31;
    const int lane4 = lane & 3, laned4 = lane >> 2;
    const int wm = warp & 1;       // row-half: rows 32*wm .. +32
    const int wn = warp >> 1;      // col-slice: cols 16*wn .. +16

    // ---- stage W1 transposed into smem as fp16 (once per block) ----
    for (int i = tid; i < 128 * 64; i += 256) {
        int k = i >> 6, n = i & 63;
        sW1t[n * PAD_A2 + k] = __float2half_rn(We1[i]);
    }

    // ---- W2 slice in registers (fp16 pairs) ----
    unsigned wb2[4][2][2];
#pragma unroll
    for (int kt = 0; kt < 4; kt++)
#pragma unroll
        for (int nt = 0; nt < 2; nt++) {
            int n = wn * 16 + nt * 8 + laned4;
            int k = kt * 16 + 2 * lane4;
            wb2[kt][nt][0] = h2u(__floats2half2_rn(We2[k * 64 + n], We2[(k + 1) * 64 + n]));
            wb2[kt][nt][1] = h2u(__floats2half2_rn(We2[(k + 8) * 64 + n], We2[(k + 9) * 64 + n]));
        }
    float bias1[2][2], bias2[2][2], wf[2][2];
#pragma unroll
    for (int nt = 0; nt < 2; nt++) {
        int c = wn * 16 + nt * 8 + 2 * lane4;
        bias1[nt][0] = be1[c]; bias1[nt][1] = be1[c + 1];
        bias2[nt][0] = be2[c]; bias2[nt][1] = be2[c + 1];
        wf[nt][0]    = Winf[c]; wf[nt][1]   = Winf[c + 1];
    }
    const float binf0 = binf[0];

    // ---- ldmatrix per-lane base offsets (bytes) ----
    unsigned sA_s  = (unsigned)__cvta_generic_to_shared(sA);
    unsigned sW1_s = (unsigned)__cvta_generic_to_shared(sW1t);
    unsigned sH_s  = (unsigned)__cvta_generic_to_shared(sH);
    const int al = lane & 15, ah = lane >> 4;       // A: rows 0..15, col 16B block
    const unsigned aoff1 = sA_s + ((wm * 32 + al) * PAD_A2 + ah * 8) * 2;
    const unsigned aoff2 = sH_s + ((wm * 32 + al) * PAD_H2 + ah * 8) * 2;
    const int bl = lane & 15;                       // B: lanes 0-15 used
    const unsigned boff1 = sW1_s + ((wn * 16 + (bl & 7)) * PAD_A2 + (bl >> 3) * 8) * 2;

    const int se = tid >> 2;   // staging: edge id 0..63
    const int sp = tid & 3;    // staging: quarter 0..3

    const int ntiles = NE / TILE_E;
    for (int t = blockIdx.x; t < ntiles; t += gridDim.x) {
        const int base = t * TILE_E;
        __syncthreads();   // prev tile fully consumed (sA reads, sE/sDis/sDst reads)

        // ---- stage per-edge scalars ----
        if (tid < 64) {
            int s = edge_index[base + tid];
            int d = edge_index[NE + base + tid];
            sDst[tid] = d;
            float dx = x[d * 3 + 0] - x[s * 3 + 0];
            float dy = x[d * 3 + 1] - x[s * 3 + 1];
            float dz = x[d * 3 + 2] - x[s * 3 + 2];
            float dd = dx * dx + dy * dy + dz * dz;
            sDis[tid] = fast_sigmoid(30.0f / (sqrtf(dd) + 1e-8f));
            sE[tid] = binf0;
        }
        // ---- stage sA = fp16([h[dst] | h[src]]), 4 threads per edge ----
        {
            int s = edge_index[base + se];
            int d = edge_index[NE + base + se];
            const float* srcp = (sp < 2) ? (h + (size_t)d * H) : (h + (size_t)s * H);
            int off = (sp & 1) * 32;
            half* dstp = sA + se * PAD_A2 + (sp >> 1) * 64 + off;
#pragma unroll
            for (int j = 0; j < 4; j++) {
                float4 v0 = *reinterpret_cast<const float4*>(srcp + off + j * 8);
                float4 v1 = *reinterpret_cast<const float4*>(srcp + off + j * 8 + 4);
                uint4 u;
                u.x = h2u(__floats2half2_rn(v0.x, v0.y));
                u.y = h2u(__floats2half2_rn(v0.z, v0.w));
                u.z = h2u(__floats2half2_rn(v1.x, v1.y));
                u.w = h2u(__floats2half2_rn(v1.z, v1.w));
                *reinterpret_cast<uint4*>(dstp + j * 8) = u;
            }
        }
        __syncthreads();

        // ---- GEMM1: [64x128] @ [128x64], K=16 per MMA ----
        float acc[2][2][4];
#pragma unroll
        for (int mt = 0; mt < 2; mt++)
#pragma unroll
            for (int nt = 0; nt < 2; nt++) {
                acc[mt][nt][0] = bias1[nt][0]; acc[mt][nt][1] = bias1[nt][1];
                acc[mt][nt][2] = bias1[nt][0]; acc[mt][nt][3] = bias1[nt][1];
            }
#pragma unroll
        for (int kt = 0; kt < 8; kt++) {
            unsigned bf0[2], bf1[2];
            ldmx2(bf0, boff1 + (kt * 16) * 2);
            ldmx2(bf1, boff1 + (8 * PAD_A2 + kt * 16) * 2);
#pragma unroll
            for (int mt = 0; mt < 2; mt++) {
                unsigned a[4];
                ldmx4(a, aoff1 + (mt * 16 * PAD_A2 + kt * 16) * 2);
                mma_f16(acc[mt][0], a, bf0);
                mma_f16(acc[mt][1], a, bf1);
            }
        }
        // relu -> sH (fp16, A-operand of GEMM2)
#pragma unroll
        for (int mt = 0; mt < 2; mt++) {
            int r = wm * 32 + mt * 16 + laned4;
#pragma unroll
            for (int nt = 0; nt < 2; nt++) {
                int c = wn * 16 + nt * 8 + 2 * lane4;
                *reinterpret_cast<half2*>(sH + r * PAD_H2 + c) =
                    __floats2half2_rn(fmaxf(acc[mt][nt][0], 0.0f), fmaxf(acc[mt][nt][1], 0.0f));
                *reinterpret_cast<half2*>(sH + (r + 8) * PAD_H2 + c) =
                    __floats2half2_rn(fmaxf(acc[mt][nt][2], 0.0f), fmaxf(acc[mt][nt][3], 0.0f));
            }
        }
        __syncthreads();

        // ---- GEMM2: [64x64] @ [64x64], B in registers ----
        float macc[2][2][4];
#pragma unroll
        for (int mt = 0; mt < 2; mt++)
#pragma unroll
            for (int nt = 0; nt < 2; nt++) {
                macc[mt][nt][0] = bias2[nt][0]; macc[mt][nt][1] = bias2[nt][1];
                macc[mt][nt][2] = bias2[nt][0]; macc[mt][nt][3] = bias2[nt][1];
            }
#pragma unroll
        for (int kt = 0; kt < 4; kt++) {
#pragma unroll
            for (int mt = 0; mt < 2; mt++) {
                unsigned a[4];
                ldmx4(a, aoff2 + (mt * 16 * PAD_H2 + kt * 16) * 2);
                mma_f16(macc[mt][0], a, wb2[kt][0]);
                mma_f16(macc[mt][1], a, wb2[kt][1]);
            }
        }

        // ---- relu (regs) + gate partial: eij = mij . Winf ----
#pragma unroll
        for (int mt = 0; mt < 2; mt++) {
            int r = wm * 32 + mt * 16 + laned4;
            float plo = 0.0f, phi = 0.0f;
#pragma unroll
            for (int nt = 0; nt < 2; nt++) {
                macc[mt][nt][0] = fmaxf(macc[mt][nt][0], 0.0f);
                macc[mt][nt][1] = fmaxf(macc[mt][nt][1], 0.0f);
                macc[mt][nt][2] = fmaxf(macc[mt][nt][2], 0.0f);
                macc[mt][nt][3] = fmaxf(macc[mt][nt][3], 0.0f);
                plo += macc[mt][nt][0] * wf[nt][0] + macc[mt][nt][1] * wf[nt][1];
                phi += macc[mt][nt][2] * wf[nt][0] + macc[mt][nt][3] * wf[nt][1];
            }
            plo += __shfl_xor_sync(0xffffffffu, plo, 1);
            plo += __shfl_xor_sync(0xffffffffu, plo, 2);
            phi += __shfl_xor_sync(0xffffffffu, phi, 1);
            phi += __shfl_xor_sync(0xffffffffu, phi, 2);
            if (lane4 == 0) {
                atomicAdd(&sE[r], plo);
                atomicAdd(&sE[r + 8], phi);
            }
        }
        __syncthreads();   // sE atomics + all sH reads complete

        // ---- gate weight per row (redundant per quad, cheap) + direct scatter ----
#pragma unroll
        for (int mt = 0; mt < 2; mt++) {
            int r = wm * 32 + mt * 16 + laned4;
            float w1 = fast_sigmoid(sE[r] * sDis[r]);
            float w2 = fast_sigmoid(sE[r + 8] * sDis[r + 8]);
            float* p1 = g_mi + (size_t)sDst[r] * H;
            float* p2 = g_mi + (size_t)sDst[r + 8] * H;
#pragma unroll
            for (int nt = 0; nt < 2; nt++) {
                int c = wn * 16 + nt * 8 + 2 * lane4;
                asm volatile("red.global.add.v2.f32 [%0], {%1,%2};"
                             :: "l"(p1 + c), "f"(macc[mt][nt][0] * w1), "f"(macc[mt][nt][1] * w1)
                             : "memory");
                asm volatile("red.global.add.v2.f32 [%0], {%1,%2};"
                             :: "l"(p2 + c), "f"(macc[mt][nt][2] * w2), "f"(macc[mt][nt][3] * w2)
                             : "memory");
            }
        }
    }
}

// ---------------------------------------------------------------------------
// Node kernel: unchanged FFMA design (small fraction of runtime)
// ---------------------------------------------------------------------------
#define WARPS 8
#define EPT 8
#define NK_SMEM_FLOATS (8448 + 4352 + 256 + 8192 + 4096)
#define NK_SMEM_BYTES  (NK_SMEM_FLOATS * 4)

__global__ void __launch_bounds__(256, 2) node_kernel(
    const float* __restrict__ h,
    const float* __restrict__ Wn1, const float* __restrict__ bn1,
    const float* __restrict__ Wn2, const float* __restrict__ bn2,
    const float* __restrict__ lng, const float* __restrict__ lnb,
    float* __restrict__ out)
{
    extern __shared__ float smem[];
    float* sW1 = smem;
    float* sW2 = sW1 + 64 * 132;
    float* sB1 = sW2 + 64 * 68;
    float* sB2 = sB1 + 64;
    float* sG  = sB2 + 64;
    float* sB  = sG + 64;
    float* sIn = sB + 64;
    float* sT  = sIn + 8 * 1024;

    const int tid = threadIdx.x;
    for (int i = tid; i < 128 * 64; i += 256) {
        int k = i >> 6, c = i & 63;
        sW1[c * 132 + k] = Wn1[i];
    }
    for (int i = tid; i < 64 * 64; i += 256) {
        int k = i >> 6, c = i & 63;
        sW2[c * 68 + k] = Wn2[i];
    }
    if (tid < 64) { sB1[tid] = bn1[tid]; sB2[tid] = bn2[tid]; sG[tid] = lng[tid]; sB[tid] = lnb[tid]; }
    __syncthreads();

    const int warp = tid >> 5, lane = tid & 31;
    const int c0 = lane, c1 = lane + 32;
    const float b1_0 = sB1[c0], b1_1 = sB1[c1];
    const float b2_0 = sB2[c0], b2_1 = sB2[c1];
    const float g0 = sG[c0], g1 = sG[c1];
    const float bb0 = sB[c0], bb1 = sB[c1];
    float* myIn = sIn + warp * 1024;
    float* myT  = sT + warp * 512;

    const int gw = blockIdx.x * WARPS + warp;
    const int nwarps = gridDim.x * WARPS;

    for (int base = gw * EPT; base < NN; base += nwarps * EPT) {
#pragma unroll
        for (int e = 0; e < EPT; e++) {
            const float* mip = g_mi + (size_t)(base + e) * H;
            const float* hp  = h + (size_t)(base + e) * H;
            *reinterpret_cast<float2*>(myIn + e * 128 + 2 * lane) =
                *reinterpret_cast<const float2*>(mip + 2 * lane);
            *reinterpret_cast<float2*>(myIn + e * 128 + 64 + 2 * lane) =
                *reinterpret_cast<const float2*>(hp + 2 * lane);
        }
        __syncwarp();

        float a0[EPT], a1[EPT];
#pragma unroll
        for (int e = 0; e < EPT; e++) { a0[e] = b1_0; a1[e] = b1_1; }
#pragma unroll 2
        for (int k = 0; k < 128; k += 4) {
            float4 w0 = *reinterpret_cast<const float4*>(sW1 + c0 * 132 + k);
            float4 w1 = *reinterpret_cast<const float4*>(sW1 + c1 * 132 + k);
#pragma unroll
            for (int e = 0; e < EPT; e++) {
                float4 v = *reinterpret_cast<const float4*>(myIn + e * 128 + k);
                a0[e] = fmaf(v.x, w0.x, a0[e]); a0[e] = fmaf(v.y, w0.y, a0[e]);
                a0[e] = fmaf(v.z, w0.z, a0[e]); a0[e] = fmaf(v.w, w0.w, a0[e]);
                a1[e] = fmaf(v.x, w1.x, a1[e]); a1[e] = fmaf(v.y, w1.y, a1[e]);
                a1[e] = fmaf(v.z, w1.z, a1[e]); a1[e] = fmaf(v.w, w1.w, a1[e]);
            }
        }
#pragma unroll
        for (int e = 0; e < EPT; e++) {
            myT[e * 64 + c0] = fmaxf(a0[e], 0.0f);
            myT[e * 64 + c1] = fmaxf(a1[e], 0.0f);
        }
        __syncwarp();

        float u0[EPT], u1[EPT];
#pragma unroll
        for (int e = 0; e < EPT; e++) { u0[e] = b2_0; u1[e] = b2_1; }
#pragma unroll 2
        for (int k = 0; k < 64; k += 4) {
            float4 w0 = *reinterpret_cast<const float4*>(sW2 + c0 * 68 + k);
            float4 w1 = *reinterpret_cast<const float4*>(sW2 + c1 * 68 + k);
#pragma unroll
            for (int e = 0; e < EPT; e++) {
                float4 v = *reinterpret_cast<const float4*>(myT + e * 64 + k);
                u0[e] = fmaf(v.x, w0.x, u0[e]); u0[e] = fmaf(v.y, w0.y, u0[e]);
                u0[e] = fmaf(v.z, w0.z, u0[e]); u0[e] = fmaf(v.w, w0.w, u0[e]);
                u1[e] = fmaf(v.x, w1.x, u1[e]); u1[e] = fmaf(v.y, w1.y, u1[e]);
                u1[e] = fmaf(v.z, w1.z, u1[e]); u1[e] = fmaf(v.w, w1.w, u1[e]);
            }
        }

#pragma unroll
        for (int e = 0; e < EPT; e++) {
            float z0 = u0[e] + myIn[e * 128 + 64 + c0];
            float z1 = u1[e] + myIn[e * 128 + 64 + c1];
            float s = z0 + z1;
            float q = z0 * z0 + z1 * z1;
#pragma unroll
            for (int o = 16; o > 0; o >>= 1) {
                s += __shfl_xor_sync(0xffffffffu, s, o);
                q += __shfl_xor_sync(0xffffffffu, q, o);
            }
            float mean = s * (1.0f / 64.0f);
            float var = q * (1.0f / 64.0f) - mean * mean;
            float inv = rsqrtf(var + 1e-5f);
            size_t ro = (size_t)(base + e) * H;
            out[ro + c0] = (z0 - mean) * inv * g0 + bb0;
            out[ro + c1] = (z1 - mean) * inv * g1 + bb1;
        }
        __syncwarp();
    }
}

__global__ void copy_x_kernel(const float4* __restrict__ x, float4* __restrict__ out)
{
    int i = blockIdx.x * blockDim.x + threadIdx.x;
    if (i < (NN * 3) / 4) out[i] = x[i];
}

extern "C" void kernel_launch(void* const* d_in, const int* in_sizes, int n_in,
                              void* d_out, int out_size)
{
    const float* h    = (const float*)d_in[0];
    const float* x    = (const float*)d_in[1];
    const int*   ei   = (const int*)d_in[2];
    const float* We1  = (const float*)d_in[3];
    const float* be1  = (const float*)d_in[4];
    const float* We2  = (const float*)d_in[5];
    const float* be2  = (const float*)d_in[6];
    const float* Winf = (const float*)d_in[7];
    const float* binf = (const float*)d_in[8];
    const float* Wn1  = (const float*)d_in[9];
    const float* bn1  = (const float*)d_in[10];
    const float* Wn2  = (const float*)d_in[11];
    const float* bn2  = (const float*)d_in[12];
    const float* lng  = (const float*)d_in[13];
    const float* lnb  = (const float*)d_in[14];
    float* out = (float*)d_out;

    void* mi_ptr = nullptr;
    cudaGetSymbolAddress(&mi_ptr, g_mi);
    cudaMemsetAsync(mi_ptr, 0, sizeof(float) * (size_t)NN * H, 0);

    cudaFuncSetAttribute(edge_mma_kernel, cudaFuncAttributeMaxDynamicSharedMemorySize, EK_SMEM_BYTES);
    cudaFuncSetAttribute(node_kernel, cudaFuncAttributeMaxDynamicSharedMemorySize, NK_SMEM_BYTES);

    edge_mma_kernel<<<296, 256, EK_SMEM_BYTES>>>(h, x, ei, We1, be1, We2, be2, Winf, binf);
    node_kernel<<<296, 256, NK_SMEM_BYTES>>>(h, Wn1, bn1, Wn2, bn2, lng, lnb, out);

    if (out_size >= NN * H + NN * 3) {
        copy_x_kernel<<<(NN * 3 / 4 + 255) / 256, 256>>>((const float4*)x,
                                                         (float4*)(out + (size_t)NN * H));
    }
}

// round 7
// speedup vs baseline: 2.7343x; 1.2788x over previous
#include <cuda_runtime.h>
#include <cuda_fp16.h>
#include <cstdint>

#define H 64
#define NN 100000
#define NE 1600000

// device-global scratch (no allocation allowed)
__device__ float g_mi[(size_t)NN * H];
__device__ half  g_h16[(size_t)NN * H];

__device__ __forceinline__ float fast_sigmoid(float z) {
    return 1.0f / (1.0f + __expf(-z));
}
__device__ __forceinline__ void mma_f16(float c[4], const unsigned a[4], const unsigned b[2]) {
    asm volatile("mma.sync.aligned.m16n8k16.row.col.f32.f16.f16.f32 "
        "{%0,%1,%2,%3}, {%4,%5,%6,%7}, {%8,%9}, {%0,%1,%2,%3};"
        : "+f"(c[0]), "+f"(c[1]), "+f"(c[2]), "+f"(c[3])
        : "r"(a[0]), "r"(a[1]), "r"(a[2]), "r"(a[3]), "r"(b[0]), "r"(b[1]));
}
__device__ __forceinline__ void ldmx4(unsigned a[4], unsigned saddr) {
    asm volatile("ldmatrix.sync.aligned.m8n8.x4.shared.b16 {%0,%1,%2,%3}, [%4];"
        : "=r"(a[0]), "=r"(a[1]), "=r"(a[2]), "=r"(a[3]) : "r"(saddr));
}
__device__ __forceinline__ unsigned h2u(half2 v) { return *reinterpret_cast<unsigned*>(&v); }
__device__ __forceinline__ void cpasync16(unsigned dst, const void* src) {
    asm volatile("cp.async.cg.shared.global [%0], [%1], 16;" :: "r"(dst), "l"(src));
}

// ---------------------------------------------------------------------------
// Edge kernel: fp16 MMA, cp.async double-buffered gathers, weights in regs
// ---------------------------------------------------------------------------
#define TILE_E 64
#define PAD_A2 136   // halfs/row: 272B; conflict-free ldmatrix
#define PAD_H2 72    // halfs/row: 144B
#define SA_BYTES (64 * PAD_A2 * 2)
#define SH_BYTES (64 * PAD_H2 * 2)
// sA[2] | sH | sDis[2][64] f | sE[2][64] f | sDst[2][64] i
#define EK_SMEM_BYTES (2*SA_BYTES + SH_BYTES + 2*64*4*3)

__global__ void __launch_bounds__(256, 2) edge_mma_kernel(
    const float* __restrict__ x,
    const int* __restrict__ edge_index,
    const float* __restrict__ We1, const float* __restrict__ be1,
    const float* __restrict__ We2, const float* __restrict__ be2,
    const float* __restrict__ Winf, const float* __restrict__ binf)
{
    extern __shared__ char smraw[];
    half*  sA0  = (half*)smraw;                 // [64][136] buffer 0
    half*  sA1  = sA0 + 64 * PAD_A2;            // [64][136] buffer 1
    half*  sH   = sA1 + 64 * PAD_A2;            // [64][72]
    float* sDis = (float*)(sH + 64 * PAD_H2);   // [2][64]
    float* sE   = sDis + 128;                   // [2][64]
    int*   sDst = (int*)(sE + 128);             // [2][64]

    const int tid  = threadIdx.x;
    const int warp = tid >> 5, lane = tid & 31;
    const int lane4 = lane & 3, laned4 = lane >> 2;
    const int wm = warp & 1;       // row-half: rows 32*wm .. +32
    const int wn = warp >> 1;      // col-slice: cols 16*wn .. +16

    // ---- W1, W2 slices in registers (fp16 frag pairs) ----
    unsigned wb1[8][2][2];
#pragma unroll
    for (int kt = 0; kt < 8; kt++)
#pragma unroll
        for (int nt = 0; nt < 2; nt++) {
            int n = wn * 16 + nt * 8 + laned4;
            int k = kt * 16 + 2 * lane4;
            wb1[kt][nt][0] = h2u(__floats2half2_rn(We1[k * 64 + n], We1[(k + 1) * 64 + n]));
            wb1[kt][nt][1] = h2u(__floats2half2_rn(We1[(k + 8) * 64 + n], We1[(k + 9) * 64 + n]));
        }
    unsigned wb2[4][2][2];
#pragma unroll
    for (int kt = 0; kt < 4; kt++)
#pragma unroll
        for (int nt = 0; nt < 2; nt++) {
            int n = wn * 16 + nt * 8 + laned4;
            int k = kt * 16 + 2 * lane4;
            wb2[kt][nt][0] = h2u(__floats2half2_rn(We2[k * 64 + n], We2[(k + 1) * 64 + n]));
            wb2[kt][nt][1] = h2u(__floats2half2_rn(We2[(k + 8) * 64 + n], We2[(k + 9) * 64 + n]));
        }
    float bias1[2][2], bias2[2][2], wf[2][2];
#pragma unroll
    for (int nt = 0; nt < 2; nt++) {
        int c = wn * 16 + nt * 8 + 2 * lane4;
        bias1[nt][0] = be1[c]; bias1[nt][1] = be1[c + 1];
        bias2[nt][0] = be2[c]; bias2[nt][1] = be2[c + 1];
        wf[nt][0]    = Winf[c]; wf[nt][1]   = Winf[c + 1];
    }
    const float binf0 = binf[0];

    // ---- ldmatrix per-lane base offsets (bytes) ----
    unsigned sA0_s = (unsigned)__cvta_generic_to_shared(sA0);
    unsigned sA1_s = (unsigned)__cvta_generic_to_shared(sA1);
    unsigned sH_s  = (unsigned)__cvta_generic_to_shared(sH);
    const int al = lane & 15, ah = lane >> 4;
    const unsigned aoff[2] = {
        sA0_s + (unsigned)(((wm * 32 + al) * PAD_A2 + ah * 8) * 2),
        sA1_s + (unsigned)(((wm * 32 + al) * PAD_A2 + ah * 8) * 2)
    };
    const unsigned aoff2 = sH_s + ((wm * 32 + al) * PAD_H2 + ah * 8) * 2;

    const int se = tid >> 2;   // gather: edge id 0..63
    const int sp = tid & 3;    // gather: quarter 0..3 (each 32 halves = 64B)
    const unsigned sAdst[2] = {
        sA0_s + (unsigned)((se * PAD_A2 + sp * 32) * 2),
        sA1_s + (unsigned)((se * PAD_A2 + sp * 32) * 2)
    };

    // prefetch tile t into buffer b
    auto prefetch = [&](int t, int b) {
        const int base = t * TILE_E;
        int s = edge_index[base + se];
        int d = edge_index[NE + base + se];
        const half* srcp = g_h16 + (size_t)((sp < 2) ? d : s) * H + (sp & 1) * 32;
        unsigned dp = sAdst[b];
#pragma unroll
        for (int j = 0; j < 4; j++) cpasync16(dp + j * 16, srcp + j * 8);
        asm volatile("cp.async.commit_group;");
        if (tid < 64) {
            int s2 = edge_index[base + tid];
            int d2 = edge_index[NE + base + tid];
            sDst[b * 64 + tid] = d2;
            float dx = x[d2 * 3 + 0] - x[s2 * 3 + 0];
            float dy = x[d2 * 3 + 1] - x[s2 * 3 + 1];
            float dz = x[d2 * 3 + 2] - x[s2 * 3 + 2];
            float dd = dx * dx + dy * dy + dz * dz;
            sDis[b * 64 + tid] = fast_sigmoid(30.0f / (sqrtf(dd) + 1e-8f));
            sE[b * 64 + tid] = binf0;
        }
    };

    const int ntiles = NE / TILE_E;
    int t = blockIdx.x;
    if (t < ntiles) prefetch(t, 0);
    int buf = 0;

    for (; t < ntiles; t += gridDim.x, buf ^= 1) {
        asm volatile("cp.async.wait_group 0;");
        __syncthreads();   // sA[buf] + scalars[buf] visible to all

        // ---- GEMM1: [64x128] @ [128x64], A from sA[buf], B in regs ----
        float acc[2][2][4];
#pragma unroll
        for (int mt = 0; mt < 2; mt++)
#pragma unroll
            for (int nt = 0; nt < 2; nt++) {
                acc[mt][nt][0] = bias1[nt][0]; acc[mt][nt][1] = bias1[nt][1];
                acc[mt][nt][2] = bias1[nt][0]; acc[mt][nt][3] = bias1[nt][1];
            }
#pragma unroll
        for (int kt = 0; kt < 8; kt++) {
#pragma unroll
            for (int mt = 0; mt < 2; mt++) {
                unsigned a[4];
                ldmx4(a, aoff[buf] + (mt * 16 * PAD_A2 + kt * 16) * 2);
                mma_f16(acc[mt][0], a, wb1[kt][0]);
                mma_f16(acc[mt][1], a, wb1[kt][1]);
            }
        }
        // relu -> sH (fp16, A-operand of GEMM2)
#pragma unroll
        for (int mt = 0; mt < 2; mt++) {
            int r = wm * 32 + mt * 16 + laned4;
#pragma unroll
            for (int nt = 0; nt < 2; nt++) {
                int c = wn * 16 + nt * 8 + 2 * lane4;
                *reinterpret_cast<half2*>(sH + r * PAD_H2 + c) =
                    __floats2half2_rn(fmaxf(acc[mt][nt][0], 0.0f), fmaxf(acc[mt][nt][1], 0.0f));
                *reinterpret_cast<half2*>(sH + (r + 8) * PAD_H2 + c) =
                    __floats2half2_rn(fmaxf(acc[mt][nt][2], 0.0f), fmaxf(acc[mt][nt][3], 0.0f));
            }
        }

        // ---- prefetch next tile into other buffer (overlaps GEMM2+scatter) ----
        {
            int tn = t + gridDim.x;
            if (tn < ntiles) prefetch(tn, buf ^ 1);
        }
        __syncthreads();   // sH ready

        // ---- GEMM2: [64x64] @ [64x64], B in regs ----
        float macc[2][2][4];
#pragma unroll
        for (int mt = 0; mt < 2; mt++)
#pragma unroll
            for (int nt = 0; nt < 2; nt++) {
                macc[mt][nt][0] = bias2[nt][0]; macc[mt][nt][1] = bias2[nt][1];
                macc[mt][nt][2] = bias2[nt][0]; macc[mt][nt][3] = bias2[nt][1];
            }
#pragma unroll
        for (int kt = 0; kt < 4; kt++) {
#pragma unroll
            for (int mt = 0; mt < 2; mt++) {
                unsigned a[4];
                ldmx4(a, aoff2 + (mt * 16 * PAD_H2 + kt * 16) * 2);
                mma_f16(macc[mt][0], a, wb2[kt][0]);
                mma_f16(macc[mt][1], a, wb2[kt][1]);
            }
        }

        // ---- relu (regs) + gate partial: eij = mij . Winf ----
#pragma unroll
        for (int mt = 0; mt < 2; mt++) {
            int r = wm * 32 + mt * 16 + laned4;
            float plo = 0.0f, phi = 0.0f;
#pragma unroll
            for (int nt = 0; nt < 2; nt++) {
                macc[mt][nt][0] = fmaxf(macc[mt][nt][0], 0.0f);
                macc[mt][nt][1] = fmaxf(macc[mt][nt][1], 0.0f);
                macc[mt][nt][2] = fmaxf(macc[mt][nt][2], 0.0f);
                macc[mt][nt][3] = fmaxf(macc[mt][nt][3], 0.0f);
                plo += macc[mt][nt][0] * wf[nt][0] + macc[mt][nt][1] * wf[nt][1];
                phi += macc[mt][nt][2] * wf[nt][0] + macc[mt][nt][3] * wf[nt][1];
            }
            plo += __shfl_xor_sync(0xffffffffu, plo, 1);
            plo += __shfl_xor_sync(0xffffffffu, plo, 2);
            phi += __shfl_xor_sync(0xffffffffu, phi, 1);
            phi += __shfl_xor_sync(0xffffffffu, phi, 2);
            if (lane4 == 0) {
                atomicAdd(&sE[buf * 64 + r], plo);
                atomicAdd(&sE[buf * 64 + r + 8], phi);
            }
        }
        __syncthreads();   // sE atomics + all sH reads done

        // ---- gate + direct scatter from registers ----
#pragma unroll
        for (int mt = 0; mt < 2; mt++) {
            int r = wm * 32 + mt * 16 + laned4;
            float w1 = fast_sigmoid(sE[buf * 64 + r] * sDis[buf * 64 + r]);
            float w2 = fast_sigmoid(sE[buf * 64 + r + 8] * sDis[buf * 64 + r + 8]);
            float* p1 = g_mi + (size_t)sDst[buf * 64 + r] * H;
            float* p2 = g_mi + (size_t)sDst[buf * 64 + r + 8] * H;
#pragma unroll
            for (int nt = 0; nt < 2; nt++) {
                int c = wn * 16 + nt * 8 + 2 * lane4;
                asm volatile("red.global.add.v2.f32 [%0], {%1,%2};"
                             :: "l"(p1 + c), "f"(macc[mt][nt][0] * w1), "f"(macc[mt][nt][1] * w1)
                             : "memory");
                asm volatile("red.global.add.v2.f32 [%0], {%1,%2};"
                             :: "l"(p2 + c), "f"(macc[mt][nt][2] * w2), "f"(macc[mt][nt][3] * w2)
                             : "memory");
            }
        }
    }
}

// ---------------------------------------------------------------------------
// Prologue: h (fp32) -> g_h16 (fp16)
// ---------------------------------------------------------------------------
__global__ void h2half_kernel(const float4* __restrict__ h)
{
    int i = blockIdx.x * blockDim.x + threadIdx.x;   // over NN*H/4
    if (i < NN * H / 4) {
        float4 v = h[i];
        half2* o = reinterpret_cast<half2*>(g_h16) + 2 * i;
        o[0] = __floats2half2_rn(v.x, v.y);
        o[1] = __floats2half2_rn(v.z, v.w);
    }
}

// ---------------------------------------------------------------------------
// Node kernel: FFMA design (small fraction of runtime)
// ---------------------------------------------------------------------------
#define WARPS 8
#define EPT 8
#define NK_SMEM_FLOATS (8448 + 4352 + 256 + 8192 + 4096)
#define NK_SMEM_BYTES  (NK_SMEM_FLOATS * 4)

__global__ void __launch_bounds__(256, 2) node_kernel(
    const float* __restrict__ h,
    const float* __restrict__ Wn1, const float* __restrict__ bn1,
    const float* __restrict__ Wn2, const float* __restrict__ bn2,
    const float* __restrict__ lng, const float* __restrict__ lnb,
    float* __restrict__ out)
{
    extern __shared__ float smem[];
    float* sW1 = smem;
    float* sW2 = sW1 + 64 * 132;
    float* sB1 = sW2 + 64 * 68;
    float* sB2 = sB1 + 64;
    float* sG  = sB2 + 64;
    float* sB  = sG + 64;
    float* sIn = sB + 64;
    float* sT  = sIn + 8 * 1024;

    const int tid = threadIdx.x;
    for (int i = tid; i < 128 * 64; i += 256) {
        int k = i >> 6, c = i & 63;
        sW1[c * 132 + k] = Wn1[i];
    }
    for (int i = tid; i < 64 * 64; i += 256) {
        int k = i >> 6, c = i & 63;
        sW2[c * 68 + k] = Wn2[i];
    }
    if (tid < 64) { sB1[tid] = bn1[tid]; sB2[tid] = bn2[tid]; sG[tid] = lng[tid]; sB[tid] = lnb[tid]; }
    __syncthreads();

    const int warp = tid >> 5, lane = tid & 31;
    const int c0 = lane, c1 = lane + 32;
    const float b1_0 = sB1[c0], b1_1 = sB1[c1];
    const float b2_0 = sB2[c0], b2_1 = sB2[c1];
    const float g0 = sG[c0], g1 = sG[c1];
    const float bb0 = sB[c0], bb1 = sB[c1];
    float* myIn = sIn + warp * 1024;
    float* myT  = sT + warp * 512;

    const int gw = blockIdx.x * WARPS + warp;
    const int nwarps = gridDim.x * WARPS;

    for (int base = gw * EPT; base < NN; base += nwarps * EPT) {
#pragma unroll
        for (int e = 0; e < EPT; e++) {
            const float* mip = g_mi + (size_t)(base + e) * H;
            const float* hp  = h + (size_t)(base + e) * H;
            *reinterpret_cast<float2*>(myIn + e * 128 + 2 * lane) =
                *reinterpret_cast<const float2*>(mip + 2 * lane);
            *reinterpret_cast<float2*>(myIn + e * 128 + 64 + 2 * lane) =
                *reinterpret_cast<const float2*>(hp + 2 * lane);
        }
        __syncwarp();

        float a0[EPT], a1[EPT];
#pragma unroll
        for (int e = 0; e < EPT; e++) { a0[e] = b1_0; a1[e] = b1_1; }
#pragma unroll 2
        for (int k = 0; k < 128; k += 4) {
            float4 w0 = *reinterpret_cast<const float4*>(sW1 + c0 * 132 + k);
            float4 w1 = *reinterpret_cast<const float4*>(sW1 + c1 * 132 + k);
#pragma unroll
            for (int e = 0; e < EPT; e++) {
                float4 v = *reinterpret_cast<const float4*>(myIn + e * 128 + k);
                a0[e] = fmaf(v.x, w0.x, a0[e]); a0[e] = fmaf(v.y, w0.y, a0[e]);
                a0[e] = fmaf(v.z, w0.z, a0[e]); a0[e] = fmaf(v.w, w0.w, a0[e]);
                a1[e] = fmaf(v.x, w1.x, a1[e]); a1[e] = fmaf(v.y, w1.y, a1[e]);
                a1[e] = fmaf(v.z, w1.z, a1[e]); a1[e] = fmaf(v.w, w1.w, a1[e]);
            }
        }
#pragma unroll
        for (int e = 0; e < EPT; e++) {
            myT[e * 64 + c0] = fmaxf(a0[e], 0.0f);
            myT[e * 64 + c1] = fmaxf(a1[e], 0.0f);
        }
        __syncwarp();

        float u0[EPT], u1[EPT];
#pragma unroll
        for (int e = 0; e < EPT; e++) { u0[e] = b2_0; u1[e] = b2_1; }
#pragma unroll 2
        for (int k = 0; k < 64; k += 4) {
            float4 w0 = *reinterpret_cast<const float4*>(sW2 + c0 * 68 + k);
            float4 w1 = *reinterpret_cast<const float4*>(sW2 + c1 * 68 + k);
#pragma unroll
            for (int e = 0; e < EPT; e++) {
                float4 v = *reinterpret_cast<const float4*>(myT + e * 64 + k);
                u0[e] = fmaf(v.x, w0.x, u0[e]); u0[e] = fmaf(v.y, w0.y, u0[e]);
                u0[e] = fmaf(v.z, w0.z, u0[e]); u0[e] = fmaf(v.w, w0.w, u0[e]);
                u1[e] = fmaf(v.x, w1.x, u1[e]); u1[e] = fmaf(v.y, w1.y, u1[e]);
                u1[e] = fmaf(v.w, w1.w, u1[e]); u1[e] = fmaf(v.z, w1.z, u1[e]);
            }
        }

#pragma unroll
        for (int e = 0; e < EPT; e++) {
            float z0 = u0[e] + myIn[e * 128 + 64 + c0];
            float z1 = u1[e] + myIn[e * 128 + 64 + c1];
            float s = z0 + z1;
            float q = z0 * z0 + z1 * z1;
#pragma unroll
            for (int o = 16; o > 0; o >>= 1) {
                s += __shfl_xor_sync(0xffffffffu, s, o);
                q += __shfl_xor_sync(0xffffffffu, q, o);
            }
            float mean = s * (1.0f / 64.0f);
            float var = q * (1.0f / 64.0f) - mean * mean;
            float inv = rsqrtf(var + 1e-5f);
            size_t ro = (size_t)(base + e) * H;
            out[ro + c0] = (z0 - mean) * inv * g0 + bb0;
            out[ro + c1] = (z1 - mean) * inv * g1 + bb1;
        }
        __syncwarp();
    }
}

__global__ void copy_x_kernel(const float4* __restrict__ x, float4* __restrict__ out)
{
    int i = blockIdx.x * blockDim.x + threadIdx.x;
    if (i < (NN * 3) / 4) out[i] = x[i];
}

extern "C" void kernel_launch(void* const* d_in, const int* in_sizes, int n_in,
                              void* d_out, int out_size)
{
    const float* h    = (const float*)d_in[0];
    const float* x    = (const float*)d_in[1];
    const int*   ei   = (const int*)d_in[2];
    const float* We1  = (const float*)d_in[3];
    const float* be1  = (const float*)d_in[4];
    const float* We2  = (const float*)d_in[5];
    const float* be2  = (const float*)d_in[6];
    const float* Winf = (const float*)d_in[7];
    const float* binf = (const float*)d_in[8];
    const float* Wn1  = (const float*)d_in[9];
    const float* bn1  = (const float*)d_in[10];
    const float* Wn2  = (const float*)d_in[11];
    const float* bn2  = (const float*)d_in[12];
    const float* lng  = (const float*)d_in[13];
    const float* lnb  = (const float*)d_in[14];
    float* out = (float*)d_out;

    void* mi_ptr = nullptr;
    cudaGetSymbolAddress(&mi_ptr, g_mi);
    cudaMemsetAsync(mi_ptr, 0, sizeof(float) * (size_t)NN * H, 0);
    h2half_kernel<<<(NN * H / 4 + 255) / 256, 256>>>((const float4*)h);

    cudaFuncSetAttribute(edge_mma_kernel, cudaFuncAttributeMaxDynamicSharedMemorySize, EK_SMEM_BYTES);
    cudaFuncSetAttribute(node_kernel, cudaFuncAttributeMaxDynamicSharedMemorySize, NK_SMEM_BYTES);

    edge_mma_kernel<<<296, 256, EK_SMEM_BYTES>>>(x, ei, We1, be1, We2, be2, Winf, binf);
    node_kernel<<<296, 256, NK_SMEM_BYTES>>>(h, Wn1, bn1, Wn2, bn2, lng, lnb, out);

    if (out_size >= NN * H + NN * 3) {
        copy_x_kernel<<<(NN * 3 / 4 + 255) / 256, 256>>>((const float4*)x,
                                                         (float4*)(out + (size_t)NN * H));
    }
}

// round 8
// speedup vs baseline: 3.0240x; 1.1060x over previous
#include <cuda_runtime.h>
#include <cuda_fp16.h>
#include <cstdint>

#define H 64
#define NN 100000
#define NE 1600000

// device-global scratch (no allocation allowed)
__device__ float g_mi[(size_t)NN * H];
__device__ half  g_h16[(size_t)NN * H];

__device__ __forceinline__ float fast_sigmoid(float z) {
    return 1.0f / (1.0f + __expf(-z));
}
__device__ __forceinline__ void mma_f16(float c[4], const unsigned a[4], const unsigned b[2]) {
    asm volatile("mma.sync.aligned.m16n8k16.row.col.f32.f16.f16.f32 "
        "{%0,%1,%2,%3}, {%4,%5,%6,%7}, {%8,%9}, {%0,%1,%2,%3};"
        : "+f"(c[0]), "+f"(c[1]), "+f"(c[2]), "+f"(c[3])
        : "r"(a[0]), "r"(a[1]), "r"(a[2]), "r"(a[3]), "r"(b[0]), "r"(b[1]));
}
__device__ __forceinline__ void ldmx4(unsigned a[4], unsigned saddr) {
    asm volatile("ldmatrix.sync.aligned.m8n8.x4.shared.b16 {%0,%1,%2,%3}, [%4];"
        : "=r"(a[0]), "=r"(a[1]), "=r"(a[2]), "=r"(a[3]) : "r"(saddr));
}
__device__ __forceinline__ unsigned h2u(half2 v) { return *reinterpret_cast<unsigned*>(&v); }
__device__ __forceinline__ void cpasync16(unsigned dst, const void* src) {
    asm volatile("cp.async.cg.shared.global [%0], [%1], 16;" :: "r"(dst), "l"(src));
}

// ---------------------------------------------------------------------------
// Edge kernel: fp16 MMA, 128-edge super-tiles (2x64 subtiles), double-buffered
// ---------------------------------------------------------------------------
#define TILE_E 128        // edges per iteration (2 subtiles of 64)
#define PAD_A2 136        // halfs/row: 272B; conflict-free ldmatrix
#define PAD_H2 72         // halfs/row: 144B
#define SA_BYTES (64 * PAD_A2 * 2)
#define SH_BYTES (64 * PAD_H2 * 2)
// sA[2 bufs][2 subs] | sH[2 subs] | sDis[2][128] | sE[2][128] | sDst[2][128]
#define EK_SMEM_BYTES (4*SA_BYTES + 2*SH_BYTES + 2*128*4*3)

__global__ void __launch_bounds__(256, 2) edge_mma_kernel(
    const float* __restrict__ x,
    const int* __restrict__ edge_index,
    const float* __restrict__ We1, const float* __restrict__ be1,
    const float* __restrict__ We2, const float* __restrict__ be2,
    const float* __restrict__ Winf, const float* __restrict__ binf)
{
    extern __shared__ char smraw[];
    half*  sA   = (half*)smraw;                      // [4][64][136]  (buf*2+sub)
    half*  sH   = sA + 4 * 64 * PAD_A2;              // [2][64][72]
    float* sDis = (float*)(sH + 2 * 64 * PAD_H2);    // [2][128]
    float* sE   = sDis + 256;                        // [2][128]
    int*   sDst = (int*)(sE + 256);                  // [2][128]

    const int tid  = threadIdx.x;
    const int warp = tid >> 5, lane = tid & 31;
    const int lane4 = lane & 3, laned4 = lane >> 2;
    const int wm = warp & 1;       // row-half: rows 32*wm .. +32 (within subtile)
    const int wn = warp >> 1;      // col-slice: cols 16*wn .. +16

    // ---- W1, W2 slices in registers (fp16 frag pairs) ----
    unsigned wb1[8][2][2];
#pragma unroll
    for (int kt = 0; kt < 8; kt++)
#pragma unroll
        for (int nt = 0; nt < 2; nt++) {
            int n = wn * 16 + nt * 8 + laned4;
            int k = kt * 16 + 2 * lane4;
            wb1[kt][nt][0] = h2u(__floats2half2_rn(We1[k * 64 + n], We1[(k + 1) * 64 + n]));
            wb1[kt][nt][1] = h2u(__floats2half2_rn(We1[(k + 8) * 64 + n], We1[(k + 9) * 64 + n]));
        }
    unsigned wb2[4][2][2];
#pragma unroll
    for (int kt = 0; kt < 4; kt++)
#pragma unroll
        for (int nt = 0; nt < 2; nt++) {
            int n = wn * 16 + nt * 8 + laned4;
            int k = kt * 16 + 2 * lane4;
            wb2[kt][nt][0] = h2u(__floats2half2_rn(We2[k * 64 + n], We2[(k + 1) * 64 + n]));
            wb2[kt][nt][1] = h2u(__floats2half2_rn(We2[(k + 8) * 64 + n], We2[(k + 9) * 64 + n]));
        }
    float bias1[2][2], bias2[2][2], wf[2][2];
#pragma unroll
    for (int nt = 0; nt < 2; nt++) {
        int c = wn * 16 + nt * 8 + 2 * lane4;
        bias1[nt][0] = be1[c]; bias1[nt][1] = be1[c + 1];
        bias2[nt][0] = be2[c]; bias2[nt][1] = be2[c + 1];
        wf[nt][0]    = Winf[c]; wf[nt][1]   = Winf[c + 1];
    }
    const float binf0 = binf[0];

    // ---- per-lane ldmatrix offsets ----
    unsigned sA_s = (unsigned)__cvta_generic_to_shared(sA);
    unsigned sH_s = (unsigned)__cvta_generic_to_shared(sH);
    const int al = lane & 15, ah = lane >> 4;
    const unsigned aoff_l  = (unsigned)(((wm * 32 + al) * PAD_A2 + ah * 8) * 2); // within region
    const unsigned hoff_l  = (unsigned)(((wm * 32 + al) * PAD_H2 + ah * 8) * 2);

    const int se = tid >> 2;   // gather: edge id 0..63 (per subtile)
    const int sp = tid & 3;    // gather: quarter (32 halves = 64B)
    const unsigned gdst_l = (unsigned)((se * PAD_A2 + sp * 32) * 2);

    // prefetch super-tile t into buffer b (both subtiles)
    auto prefetch = [&](int t, int b) {
        const int base = t * TILE_E;
#pragma unroll
        for (int sub = 0; sub < 2; sub++) {
            int g = base + sub * 64 + se;
            int s = edge_index[g];
            int d = edge_index[NE + g];
            const half* srcp = g_h16 + (size_t)((sp < 2) ? d : s) * H + (sp & 1) * 32;
            unsigned dp = sA_s + (unsigned)((b * 2 + sub) * SA_BYTES) + gdst_l;
#pragma unroll
            for (int j = 0; j < 4; j++) cpasync16(dp + j * 16, srcp + j * 8);
        }
        asm volatile("cp.async.commit_group;");
        if (tid < 128) {
            int s2 = edge_index[base + tid];
            int d2 = edge_index[NE + base + tid];
            sDst[b * 128 + tid] = d2;
            float dx = x[d2 * 3 + 0] - x[s2 * 3 + 0];
            float dy = x[d2 * 3 + 1] - x[s2 * 3 + 1];
            float dz = x[d2 * 3 + 2] - x[s2 * 3 + 2];
            float dd = dx * dx + dy * dy + dz * dz;
            sDis[b * 128 + tid] = fast_sigmoid(30.0f / (sqrtf(dd) + 1e-8f));
            sE[b * 128 + tid] = binf0;
        }
    };

    const int ntiles = NE / TILE_E;
    int t = blockIdx.x;
    if (t < ntiles) prefetch(t, 0);
    int buf = 0;

    for (; t < ntiles; t += gridDim.x, buf ^= 1) {
        asm volatile("cp.async.wait_group 0;");
        __syncthreads();   // sA[buf][*] + scalars[buf] visible

        // ---- GEMM1 on both subtiles (independent chains) ----
#pragma unroll
        for (int sub = 0; sub < 2; sub++) {
            const unsigned abase = sA_s + (unsigned)((buf * 2 + sub) * SA_BYTES) + aoff_l;
            float acc[2][2][4];
#pragma unroll
            for (int mt = 0; mt < 2; mt++)
#pragma unroll
                for (int nt = 0; nt < 2; nt++) {
                    acc[mt][nt][0] = bias1[nt][0]; acc[mt][nt][1] = bias1[nt][1];
                    acc[mt][nt][2] = bias1[nt][0]; acc[mt][nt][3] = bias1[nt][1];
                }
#pragma unroll
            for (int kt = 0; kt < 8; kt++) {
#pragma unroll
                for (int mt = 0; mt < 2; mt++) {
                    unsigned a[4];
                    ldmx4(a, abase + (mt * 16 * PAD_A2 + kt * 16) * 2);
                    mma_f16(acc[mt][0], a, wb1[kt][0]);
                    mma_f16(acc[mt][1], a, wb1[kt][1]);
                }
            }
            half* sHsub = sH + sub * 64 * PAD_H2;
#pragma unroll
            for (int mt = 0; mt < 2; mt++) {
                int r = wm * 32 + mt * 16 + laned4;
#pragma unroll
                for (int nt = 0; nt < 2; nt++) {
                    int c = wn * 16 + nt * 8 + 2 * lane4;
                    *reinterpret_cast<half2*>(sHsub + r * PAD_H2 + c) =
                        __floats2half2_rn(fmaxf(acc[mt][nt][0], 0.0f), fmaxf(acc[mt][nt][1], 0.0f));
                    *reinterpret_cast<half2*>(sHsub + (r + 8) * PAD_H2 + c) =
                        __floats2half2_rn(fmaxf(acc[mt][nt][2], 0.0f), fmaxf(acc[mt][nt][3], 0.0f));
                }
            }
        }

        // prefetch next super-tile (overlaps everything below)
        {
            int tn = t + gridDim.x;
            if (tn < ntiles) prefetch(tn, buf ^ 1);
        }
        __syncthreads();   // sH[0],sH[1] ready

        // ---- per subtile: GEMM2 -> gate -> scatter ----
#pragma unroll
        for (int sub = 0; sub < 2; sub++) {
            const unsigned hbase = sH_s + (unsigned)(sub * SH_BYTES) + hoff_l;
            float macc[2][2][4];
#pragma unroll
            for (int mt = 0; mt < 2; mt++)
#pragma unroll
                for (int nt = 0; nt < 2; nt++) {
                    macc[mt][nt][0] = bias2[nt][0]; macc[mt][nt][1] = bias2[nt][1];
                    macc[mt][nt][2] = bias2[nt][0]; macc[mt][nt][3] = bias2[nt][1];
                }
#pragma unroll
            for (int kt = 0; kt < 4; kt++) {
#pragma unroll
                for (int mt = 0; mt < 2; mt++) {
                    unsigned a[4];
                    ldmx4(a, hbase + (mt * 16 * PAD_H2 + kt * 16) * 2);
                    mma_f16(macc[mt][0], a, wb2[kt][0]);
                    mma_f16(macc[mt][1], a, wb2[kt][1]);
                }
            }

            // relu (regs) + gate partials into sE
            float* sEs = sE + buf * 128 + sub * 64;
#pragma unroll
            for (int mt = 0; mt < 2; mt++) {
                int r = wm * 32 + mt * 16 + laned4;
                float plo = 0.0f, phi = 0.0f;
#pragma unroll
                for (int nt = 0; nt < 2; nt++) {
                    macc[mt][nt][0] = fmaxf(macc[mt][nt][0], 0.0f);
                    macc[mt][nt][1] = fmaxf(macc[mt][nt][1], 0.0f);
                    macc[mt][nt][2] = fmaxf(macc[mt][nt][2], 0.0f);
                    macc[mt][nt][3] = fmaxf(macc[mt][nt][3], 0.0f);
                    plo += macc[mt][nt][0] * wf[nt][0] + macc[mt][nt][1] * wf[nt][1];
                    phi += macc[mt][nt][2] * wf[nt][0] + macc[mt][nt][3] * wf[nt][1];
                }
                plo += __shfl_xor_sync(0xffffffffu, plo, 1);
                plo += __shfl_xor_sync(0xffffffffu, plo, 2);
                phi += __shfl_xor_sync(0xffffffffu, phi, 1);
                phi += __shfl_xor_sync(0xffffffffu, phi, 2);
                if (lane4 == 0) {
                    atomicAdd(&sEs[r], plo);
                    atomicAdd(&sEs[r + 8], phi);
                }
            }
            __syncthreads();   // sE[sub] complete (also orders sH[sub] reads)

            // gate + direct scatter from registers
            float* sDs = sDis + buf * 128 + sub * 64;
            int*   sDt = sDst + buf * 128 + sub * 64;
#pragma unroll
            for (int mt = 0; mt < 2; mt++) {
                int r = wm * 32 + mt * 16 + laned4;
                float w1 = fast_sigmoid(sEs[r] * sDs[r]);
                float w2 = fast_sigmoid(sEs[r + 8] * sDs[r + 8]);
                float* p1 = g_mi + (size_t)sDt[r] * H;
                float* p2 = g_mi + (size_t)sDt[r + 8] * H;
#pragma unroll
                for (int nt = 0; nt < 2; nt++) {
                    int c = wn * 16 + nt * 8 + 2 * lane4;
                    asm volatile("red.global.add.v2.f32 [%0], {%1,%2};"
                                 :: "l"(p1 + c), "f"(macc[mt][nt][0] * w1), "f"(macc[mt][nt][1] * w1)
                                 : "memory");
                    asm volatile("red.global.add.v2.f32 [%0], {%1,%2};"
                                 :: "l"(p2 + c), "f"(macc[mt][nt][2] * w2), "f"(macc[mt][nt][3] * w2)
                                 : "memory");
                }
            }
        }
    }
}

// ---------------------------------------------------------------------------
// Prologue: h (fp32) -> g_h16 (fp16)
// ---------------------------------------------------------------------------
__global__ void h2half_kernel(const float4* __restrict__ h)
{
    int i = blockIdx.x * blockDim.x + threadIdx.x;   // over NN*H/4
    if (i < NN * H / 4) {
        float4 v = h[i];
        half2* o = reinterpret_cast<half2*>(g_h16) + 2 * i;
        o[0] = __floats2half2_rn(v.x, v.y);
        o[1] = __floats2half2_rn(v.z, v.w);
    }
}

// ---------------------------------------------------------------------------
// Node kernel: FFMA design (small fraction of runtime)
// ---------------------------------------------------------------------------
#define WARPS 8
#define EPT 8
#define NK_SMEM_FLOATS (8448 + 4352 + 256 + 8192 + 4096)
#define NK_SMEM_BYTES  (NK_SMEM_FLOATS * 4)

__global__ void __launch_bounds__(256, 2) node_kernel(
    const float* __restrict__ h,
    const float* __restrict__ Wn1, const float* __restrict__ bn1,
    const float* __restrict__ Wn2, const float* __restrict__ bn2,
    const float* __restrict__ lng, const float* __restrict__ lnb,
    float* __restrict__ out)
{
    extern __shared__ float smem[];
    float* sW1 = smem;
    float* sW2 = sW1 + 64 * 132;
    float* sB1 = sW2 + 64 * 68;
    float* sB2 = sB1 + 64;
    float* sG  = sB2 + 64;
    float* sB  = sG + 64;
    float* sIn = sB + 64;
    float* sT  = sIn + 8 * 1024;

    const int tid = threadIdx.x;
    for (int i = tid; i < 128 * 64; i += 256) {
        int k = i >> 6, c = i & 63;
        sW1[c * 132 + k] = Wn1[i];
    }
    for (int i = tid; i < 64 * 64; i += 256) {
        int k = i >> 6, c = i & 63;
        sW2[c * 68 + k] = Wn2[i];
    }
    if (tid < 64) { sB1[tid] = bn1[tid]; sB2[tid] = bn2[tid]; sG[tid] = lng[tid]; sB[tid] = lnb[tid]; }
    __syncthreads();

    const int warp = tid >> 5, lane = tid & 31;
    const int c0 = lane, c1 = lane + 32;
    const float b1_0 = sB1[c0], b1_1 = sB1[c1];
    const float b2_0 = sB2[c0], b2_1 = sB2[c1];
    const float g0 = sG[c0], g1 = sG[c1];
    const float bb0 = sB[c0], bb1 = sB[c1];
    float* myIn = sIn + warp * 1024;
    float* myT  = sT + warp * 512;

    const int gw = blockIdx.x * WARPS + warp;
    const int nwarps = gridDim.x * WARPS;

    for (int base = gw * EPT; base < NN; base += nwarps * EPT) {
#pragma unroll
        for (int e = 0; e < EPT; e++) {
            const float* mip = g_mi + (size_t)(base + e) * H;
            const float* hp  = h + (size_t)(base + e) * H;
            *reinterpret_cast<float2*>(myIn + e * 128 + 2 * lane) =
                *reinterpret_cast<const float2*>(mip + 2 * lane);
            *reinterpret_cast<float2*>(myIn + e * 128 + 64 + 2 * lane) =
                *reinterpret_cast<const float2*>(hp + 2 * lane);
        }
        __syncwarp();

        float a0[EPT], a1[EPT];
#pragma unroll
        for (int e = 0; e < EPT; e++) { a0[e] = b1_0; a1[e] = b1_1; }
#pragma unroll 2
        for (int k = 0; k < 128; k += 4) {
            float4 w0 = *reinterpret_cast<const float4*>(sW1 + c0 * 132 + k);
            float4 w1 = *reinterpret_cast<const float4*>(sW1 + c1 * 132 + k);
#pragma unroll
            for (int e = 0; e < EPT; e++) {
                float4 v = *reinterpret_cast<const float4*>(myIn + e * 128 + k);
                a0[e] = fmaf(v.x, w0.x, a0[e]); a0[e] = fmaf(v.y, w0.y, a0[e]);
                a0[e] = fmaf(v.z, w0.z, a0[e]); a0[e] = fmaf(v.w, w0.w, a0[e]);
                a1[e] = fmaf(v.x, w1.x, a1[e]); a1[e] = fmaf(v.y, w1.y, a1[e]);
                a1[e] = fmaf(v.z, w1.z, a1[e]); a1[e] = fmaf(v.w, w1.w, a1[e]);
            }
        }
#pragma unroll
        for (int e = 0; e < EPT; e++) {
            myT[e * 64 + c0] = fmaxf(a0[e], 0.0f);
            myT[e * 64 + c1] = fmaxf(a1[e], 0.0f);
        }
        __syncwarp();

        float u0[EPT], u1[EPT];
#pragma unroll
        for (int e = 0; e < EPT; e++) { u0[e] = b2_0; u1[e] = b2_1; }
#pragma unroll 2
        for (int k = 0; k < 64; k += 4) {
            float4 w0 = *reinterpret_cast<const float4*>(sW2 + c0 * 68 + k);
            float4 w1 = *reinterpret_cast<const float4*>(sW2 + c1 * 68 + k);
#pragma unroll
            for (int e = 0; e < EPT; e++) {
                float4 v = *reinterpret_cast<const float4*>(myT + e * 64 + k);
                u0[e] = fmaf(v.x, w0.x, u0[e]); u0[e] = fmaf(v.y, w0.y, u0[e]);
                u0[e] = fmaf(v.z, w0.z, u0[e]); u0[e] = fmaf(v.w, w0.w, u0[e]);
                u1[e] = fmaf(v.x, w1.x, u1[e]); u1[e] = fmaf(v.y, w1.y, u1[e]);
                u1[e] = fmaf(v.z, w1.z, u1[e]); u1[e] = fmaf(v.w, w1.w, u1[e]);
            }
        }

#pragma unroll
        for (int e = 0; e < EPT; e++) {
            float z0 = u0[e] + myIn[e * 128 + 64 + c0];
            float z1 = u1[e] + myIn[e * 128 + 64 + c1];
            float s = z0 + z1;
            float q = z0 * z0 + z1 * z1;
#pragma unroll
            for (int o = 16; o > 0; o >>= 1) {
                s += __shfl_xor_sync(0xffffffffu, s, o);
                q += __shfl_xor_sync(0xffffffffu, q, o);
            }
            float mean = s * (1.0f / 64.0f);
            float var = q * (1.0f / 64.0f) - mean * mean;
            float inv = rsqrtf(var + 1e-5f);
            size_t ro = (size_t)(base + e) * H;
            out[ro + c0] = (z0 - mean) * inv * g0 + bb0;
            out[ro + c1] = (z1 - mean) * inv * g1 + bb1;
        }
        __syncwarp();
    }
}

__global__ void copy_x_kernel(const float4* __restrict__ x, float4* __restrict__ out)
{
    int i = blockIdx.x * blockDim.x + threadIdx.x;
    if (i < (NN * 3) / 4) out[i] = x[i];
}

extern "C" void kernel_launch(void* const* d_in, const int* in_sizes, int n_in,
                              void* d_out, int out_size)
{
    const float* h    = (const float*)d_in[0];
    const float* x    = (const float*)d_in[1];
    const int*   ei   = (const int*)d_in[2];
    const float* We1  = (const float*)d_in[3];
    const float* be1  = (const float*)d_in[4];
    const float* We2  = (const float*)d_in[5];
    const float* be2  = (const float*)d_in[6];
    const float* Winf = (const float*)d_in[7];
    const float* binf = (const float*)d_in[8];
    const float* Wn1  = (const float*)d_in[9];
    const float* bn1  = (const float*)d_in[10];
    const float* Wn2  = (const float*)d_in[11];
    const float* bn2  = (const float*)d_in[12];
    const float* lng  = (const float*)d_in[13];
    const float* lnb  = (const float*)d_in[14];
    float* out = (float*)d_out;

    void* mi_ptr = nullptr;
    cudaGetSymbolAddress(&mi_ptr, g_mi);
    cudaMemsetAsync(mi_ptr, 0, sizeof(float) * (size_t)NN * H, 0);
    h2half_kernel<<<(NN * H / 4 + 255) / 256, 256>>>((const float4*)h);

    cudaFuncSetAttribute(edge_mma_kernel, cudaFuncAttributeMaxDynamicSharedMemorySize, EK_SMEM_BYTES);
    cudaFuncSetAttribute(node_kernel, cudaFuncAttributeMaxDynamicSharedMemorySize, NK_SMEM_BYTES);

    edge_mma_kernel<<<296, 256, EK_SMEM_BYTES>>>(x, ei, We1, be1, We2, be2, Winf, binf);
    node_kernel<<<296, 256, NK_SMEM_BYTES>>>(h, Wn1, bn1, Wn2, bn2, lng, lnb, out);

    if (out_size >= NN * H + NN * 3) {
        copy_x_kernel<<<(NN * 3 / 4 + 255) / 256, 256>>>((const float4*)x,
                                                         (float4*)(out + (size_t)NN * H));
    }
}

// round 9
// speedup vs baseline: 3.2256x; 1.0667x over previous
#include <cuda_runtime.h>
#include <cuda_fp16.h>
#include <cstdint>

#define H 64
#define NN 100000
#define NE 1600000

// device-global scratch (no allocation allowed)
__device__ float g_mi[(size_t)NN * H];
__device__ half  g_p[(size_t)NN * 128];   // [P1 | P2] per node

__device__ __forceinline__ float fast_sigmoid(float z) {
    return 1.0f / (1.0f + __expf(-z));
}
__device__ __forceinline__ void mma_f16(float c[4], const unsigned a[4], const unsigned b[2]) {
    asm volatile("mma.sync.aligned.m16n8k16.row.col.f32.f16.f16.f32 "
        "{%0,%1,%2,%3}, {%4,%5,%6,%7}, {%8,%9}, {%0,%1,%2,%3};"
        : "+f"(c[0]), "+f"(c[1]), "+f"(c[2]), "+f"(c[3])
        : "r"(a[0]), "r"(a[1]), "r"(a[2]), "r"(a[3]), "r"(b[0]), "r"(b[1]));
}
__device__ __forceinline__ void ldmx4(unsigned a[4], unsigned saddr) {
    asm volatile("ldmatrix.sync.aligned.m8n8.x4.shared.b16 {%0,%1,%2,%3}, [%4];"
        : "=r"(a[0]), "=r"(a[1]), "=r"(a[2]), "=r"(a[3]) : "r"(saddr));
}
__device__ __forceinline__ unsigned h2u(half2 v) { return *reinterpret_cast<unsigned*>(&v); }
__device__ __forceinline__ void cpasync16(unsigned dst, const void* src) {
    asm volatile("cp.async.cg.shared.global [%0], [%1], 16;" :: "r"(dst), "l"(src));
}
__device__ __forceinline__ unsigned hadd2u(unsigned a, unsigned b) {
    unsigned r; asm("add.f16x2 %0, %1, %2;" : "=r"(r) : "r"(a), "r"(b)); return r;
}
__device__ __forceinline__ unsigned hrelu2u(unsigned a) {
    unsigned r; asm("max.f16x2 %0, %1, %2;" : "=r"(r) : "r"(a), "r"(0u)); return r;
}

// ---------------------------------------------------------------------------
// Precompute: g_p[n] = [ h[n]@We1_top | h[n]@We1_bot ]  (fp16 MMA, 64 nodes/blk)
// ---------------------------------------------------------------------------
__global__ void __launch_bounds__(256) precompute_kernel(
    const float* __restrict__ h, const float* __restrict__ We1)
{
    __shared__ half sAh[64 * 72];
    const int tid = threadIdx.x;
    const int warp = tid >> 5, lane = tid & 31;
    const int lane4 = lane & 3, laned4 = lane >> 2;
    const int wm = warp & 1, wn = warp >> 1;   // 32 rows x 32 out-cols per warp

    unsigned wb[4][4][2];
#pragma unroll
    for (int kt = 0; kt < 4; kt++)
#pragma unroll
        for (int nt = 0; nt < 4; nt++) {
            int j = wn * 32 + nt * 8 + laned4;      // 0..127 output col
            int k = kt * 16 + 2 * lane4;
            int kr = k + ((j >= 64) ? 64 : 0);      // top/bottom half of We1
            int jc = j & 63;
            wb[kt][nt][0] = h2u(__floats2half2_rn(We1[kr * 64 + jc], We1[(kr + 1) * 64 + jc]));
            wb[kt][nt][1] = h2u(__floats2half2_rn(We1[(kr + 8) * 64 + jc], We1[(kr + 9) * 64 + jc]));
        }

    const int node0 = blockIdx.x * 64;
    {
        int nd = tid >> 2, q = tid & 3;
        if (node0 + nd < NN) {
            const float* src = h + (size_t)(node0 + nd) * H + q * 16;
            half* dst = sAh + nd * 72 + q * 16;
#pragma unroll
            for (int j = 0; j < 4; j++) {
                float4 v = *reinterpret_cast<const float4*>(src + j * 4);
                *reinterpret_cast<half2*>(dst + j * 4)     = __floats2half2_rn(v.x, v.y);
                *reinterpret_cast<half2*>(dst + j * 4 + 2) = __floats2half2_rn(v.z, v.w);
            }
        }
    }
    __syncthreads();

    const int al = lane & 15, ah = lane >> 4;
    unsigned abase = (unsigned)__cvta_generic_to_shared(sAh) + ((wm * 32 + al) * 72 + ah * 8) * 2;
    float acc[2][4][4] = {};
#pragma unroll
    for (int kt = 0; kt < 4; kt++)
#pragma unroll
        for (int mt = 0; mt < 2; mt++) {
            unsigned a[4];
            ldmx4(a, abase + (mt * 16 * 72 + kt * 16) * 2);
#pragma unroll
            for (int nt = 0; nt < 4; nt++)
                mma_f16(acc[mt][nt], a, wb[kt][nt]);
        }
#pragma unroll
    for (int mt = 0; mt < 2; mt++)
#pragma unroll
        for (int nt = 0; nt < 4; nt++) {
            int r = wm * 32 + mt * 16 + laned4;
            int c = wn * 32 + nt * 8 + 2 * lane4;
            if (node0 + r < NN)
                *reinterpret_cast<half2*>(g_p + (size_t)(node0 + r) * 128 + c) =
                    __floats2half2_rn(acc[mt][nt][0], acc[mt][nt][1]);
            if (node0 + r + 8 < NN)
                *reinterpret_cast<half2*>(g_p + (size_t)(node0 + r + 8) * 128 + c) =
                    __floats2half2_rn(acc[mt][nt][2], acc[mt][nt][3]);
        }
}

// ---------------------------------------------------------------------------
// Edge kernel: gather P1[dst],P2[src]; fused relu(P1+P2+b) -> GEMM2 A-frags
// ---------------------------------------------------------------------------
#define TILE_E 128        // 2 subtiles of 64
#define PAD_P 136         // halves/row (272B): conflict-free ldmatrix, 16B-aligned chunks
#define SP_BYTES (64 * PAD_P * 2)
// sP[2 bufs][2 subs] | sDis[2][128] | sE[2][128] | sDst[2][128]
#define EK_SMEM_BYTES (4*SP_BYTES + 2*128*4*3)

__global__ void __launch_bounds__(256, 2) edge_mma_kernel(
    const float* __restrict__ x,
    const int* __restrict__ edge_index,
    const float* __restrict__ be1,
    const float* __restrict__ We2, const float* __restrict__ be2,
    const float* __restrict__ Winf, const float* __restrict__ binf)
{
    extern __shared__ char smraw[];
    half*  sP   = (half*)smraw;                      // [4][64][136]  (buf*2+sub)
    float* sDis = (float*)(sP + 4 * 64 * PAD_P);     // [2][128]
    float* sE   = sDis + 256;                        // [2][128]
    int*   sDst = (int*)(sE + 256);                  // [2][128]

    const int tid  = threadIdx.x;
    const int warp = tid >> 5, lane = tid & 31;
    const int lane4 = lane & 3, laned4 = lane >> 2;
    const int wm = warp & 1;       // rows 32*wm .. +32 (within subtile)
    const int wn = warp >> 1;      // cols 16*wn .. +16

    // ---- W2 slice in registers ----
    unsigned wb2[4][2][2];
#pragma unroll
    for (int kt = 0; kt < 4; kt++)
#pragma unroll
        for (int nt = 0; nt < 2; nt++) {
            int n = wn * 16 + nt * 8 + laned4;
            int k = kt * 16 + 2 * lane4;
            wb2[kt][nt][0] = h2u(__floats2half2_rn(We2[k * 64 + n], We2[(k + 1) * 64 + n]));
            wb2[kt][nt][1] = h2u(__floats2half2_rn(We2[(k + 8) * 64 + n], We2[(k + 9) * 64 + n]));
        }
    // be1 in A-fragment layout (per-k half2, lo/hi 8-k groups)
    unsigned bias1u[4][2];
#pragma unroll
    for (int kt = 0; kt < 4; kt++) {
        int k = kt * 16 + 2 * lane4;
        bias1u[kt][0] = h2u(__floats2half2_rn(be1[k], be1[k + 1]));
        bias1u[kt][1] = h2u(__floats2half2_rn(be1[k + 8], be1[k + 9]));
    }
    float bias2[2][2], wf[2][2];
#pragma unroll
    for (int nt = 0; nt < 2; nt++) {
        int c = wn * 16 + nt * 8 + 2 * lane4;
        bias2[nt][0] = be2[c]; bias2[nt][1] = be2[c + 1];
        wf[nt][0]    = Winf[c]; wf[nt][1]   = Winf[c + 1];
    }
    const float binf0 = binf[0];

    unsigned sP_s = (unsigned)__cvta_generic_to_shared(sP);
    const int al = lane & 15, ah = lane >> 4;
    const unsigned poff_l = (unsigned)(((wm * 32 + al) * PAD_P + ah * 8) * 2);

    const int se = tid >> 2;   // gather: edge id 0..63 (per subtile)
    const int sp = tid & 3;    // gather: quarter (32 halves = 64B)

    auto prefetch = [&](int t, int b) {
        const int base = t * TILE_E;
#pragma unroll
        for (int sub = 0; sub < 2; sub++) {
            int g = base + sub * 64 + se;
            int s = edge_index[g];
            int d = edge_index[NE + g];
            int idx = (sp < 2) ? d : s;          // sp 0,1: P1[dst]; sp 2,3: P2[src]
            const half* srcp = g_p + (size_t)idx * 128 + sp * 32;
            unsigned dp = sP_s + (unsigned)((b * 2 + sub) * SP_BYTES)
                        + (unsigned)((se * PAD_P + sp * 32) * 2);
#pragma unroll
            for (int j = 0; j < 4; j++) cpasync16(dp + j * 16, srcp + j * 8);
        }
        asm volatile("cp.async.commit_group;");
        if (tid < 128) {
            int s2 = edge_index[base + tid];
            int d2 = edge_index[NE + base + tid];
            sDst[b * 128 + tid] = d2;
            float dx = x[d2 * 3 + 0] - x[s2 * 3 + 0];
            float dy = x[d2 * 3 + 1] - x[s2 * 3 + 1];
            float dz = x[d2 * 3 + 2] - x[s2 * 3 + 2];
            float dd = dx * dx + dy * dy + dz * dz;
            sDis[b * 128 + tid] = fast_sigmoid(30.0f / (sqrtf(dd) + 1e-8f));
            sE[b * 128 + tid] = binf0;
        }
    };

    const int ntiles = NE / TILE_E;
    int t = blockIdx.x;
    if (t < ntiles) prefetch(t, 0);
    int buf = 0;

    for (; t < ntiles; t += gridDim.x, buf ^= 1) {
        asm volatile("cp.async.wait_group 0;");
        __syncthreads();   // sP[buf][*] + scalars[buf] visible; prev scatter done

        // prefetch next super-tile (overlaps all compute below)
        {
            int tn = t + gridDim.x;
            if (tn < ntiles) prefetch(tn, buf ^ 1);
        }

        float macc[2][2][2][4];   // [sub][mt][nt][4]
#pragma unroll
        for (int sub = 0; sub < 2; sub++) {
            const unsigned pb = sP_s + (unsigned)((buf * 2 + sub) * SP_BYTES) + poff_l;
#pragma unroll
            for (int mt = 0; mt < 2; mt++)
#pragma unroll
                for (int nt = 0; nt < 2; nt++) {
                    macc[sub][mt][nt][0] = bias2[nt][0]; macc[sub][mt][nt][1] = bias2[nt][1];
                    macc[sub][mt][nt][2] = bias2[nt][0]; macc[sub][mt][nt][3] = bias2[nt][1];
                }
            // GEMM2 with fused A = relu(P1 + P2 + be1)
#pragma unroll
            for (int kt = 0; kt < 4; kt++) {
#pragma unroll
                for (int mt = 0; mt < 2; mt++) {
                    unsigned p1[4], p2[4], a[4];
                    unsigned ab = pb + (mt * 16 * PAD_P + kt * 16) * 2;
                    ldmx4(p1, ab);
                    ldmx4(p2, ab + 128);   // P2 lives 64 halves later in the row
                    a[0] = hrelu2u(hadd2u(hadd2u(p1[0], p2[0]), bias1u[kt][0]));
                    a[1] = hrelu2u(hadd2u(hadd2u(p1[1], p2[1]), bias1u[kt][0]));
                    a[2] = hrelu2u(hadd2u(hadd2u(p1[2], p2[2]), bias1u[kt][1]));
                    a[3] = hrelu2u(hadd2u(hadd2u(p1[3], p2[3]), bias1u[kt][1]));
                    mma_f16(macc[sub][mt][0], a, wb2[kt][0]);
                    mma_f16(macc[sub][mt][1], a, wb2[kt][1]);
                }
            }

            // relu (regs) + gate partials into sE
            float* sEs = sE + buf * 128 + sub * 64;
#pragma unroll
            for (int mt = 0; mt < 2; mt++) {
                int r = wm * 32 + mt * 16 + laned4;
                float plo = 0.0f, phi = 0.0f;
#pragma unroll
                for (int nt = 0; nt < 2; nt++) {
                    macc[sub][mt][nt][0] = fmaxf(macc[sub][mt][nt][0], 0.0f);
                    macc[sub][mt][nt][1] = fmaxf(macc[sub][mt][nt][1], 0.0f);
                    macc[sub][mt][nt][2] = fmaxf(macc[sub][mt][nt][2], 0.0f);
                    macc[sub][mt][nt][3] = fmaxf(macc[sub][mt][nt][3], 0.0f);
                    plo += macc[sub][mt][nt][0] * wf[nt][0] + macc[sub][mt][nt][1] * wf[nt][1];
                    phi += macc[sub][mt][nt][2] * wf[nt][0] + macc[sub][mt][nt][3] * wf[nt][1];
                }
                plo += __shfl_xor_sync(0xffffffffu, plo, 1);
                plo += __shfl_xor_sync(0xffffffffu, plo, 2);
                phi += __shfl_xor_sync(0xffffffffu, phi, 1);
                phi += __shfl_xor_sync(0xffffffffu, phi, 2);
                if (lane4 == 0) {
                    atomicAdd(&sEs[r], plo);
                    atomicAdd(&sEs[r + 8], phi);
                }
            }
        }
        __syncthreads();   // both subs' sE complete

        // ---- gate + direct scatter from registers (both subs) ----
#pragma unroll
        for (int sub = 0; sub < 2; sub++) {
            float* sEs = sE + buf * 128 + sub * 64;
            float* sDs = sDis + buf * 128 + sub * 64;
            int*   sDt = sDst + buf * 128 + sub * 64;
#pragma unroll
            for (int mt = 0; mt < 2; mt++) {
                int r = wm * 32 + mt * 16 + laned4;
                float w1 = fast_sigmoid(sEs[r] * sDs[r]);
                float w2 = fast_sigmoid(sEs[r + 8] * sDs[r + 8]);
                float* p1 = g_mi + (size_t)sDt[r] * H;
                float* p2 = g_mi + (size_t)sDt[r + 8] * H;
#pragma unroll
                for (int nt = 0; nt < 2; nt++) {
                    int c = wn * 16 + nt * 8 + 2 * lane4;
                    asm volatile("red.global.add.v2.f32 [%0], {%1,%2};"
                                 :: "l"(p1 + c), "f"(macc[sub][mt][nt][0] * w1), "f"(macc[sub][mt][nt][1] * w1)
                                 : "memory");
                    asm volatile("red.global.add.v2.f32 [%0], {%1,%2};"
                                 :: "l"(p2 + c), "f"(macc[sub][mt][nt][2] * w2), "f"(macc[sub][mt][nt][3] * w2)
                                 : "memory");
                }
            }
        }
    }
}

// ---------------------------------------------------------------------------
// Node kernel: FFMA design (small fraction of runtime)
// ---------------------------------------------------------------------------
#define WARPS 8
#define EPT 8
#define NK_SMEM_FLOATS (8448 + 4352 + 256 + 8192 + 4096)
#define NK_SMEM_BYTES  (NK_SMEM_FLOATS * 4)

__global__ void __launch_bounds__(256, 2) node_kernel(
    const float* __restrict__ h,
    const float* __restrict__ Wn1, const float* __restrict__ bn1,
    const float* __restrict__ Wn2, const float* __restrict__ bn2,
    const float* __restrict__ lng, const float* __restrict__ lnb,
    float* __restrict__ out)
{
    extern __shared__ float smem[];
    float* sW1 = smem;
    float* sW2 = sW1 + 64 * 132;
    float* sB1 = sW2 + 64 * 68;
    float* sB2 = sB1 + 64;
    float* sG  = sB2 + 64;
    float* sB  = sG + 64;
    float* sIn = sB + 64;
    float* sT  = sIn + 8 * 1024;

    const int tid = threadIdx.x;
    for (int i = tid; i < 128 * 64; i += 256) {
        int k = i >> 6, c = i & 63;
        sW1[c * 132 + k] = Wn1[i];
    }
    for (int i = tid; i < 64 * 64; i += 256) {
        int k = i >> 6, c = i & 63;
        sW2[c * 68 + k] = Wn2[i];
    }
    if (tid < 64) { sB1[tid] = bn1[tid]; sB2[tid] = bn2[tid]; sG[tid] = lng[tid]; sB[tid] = lnb[tid]; }
    __syncthreads();

    const int warp = tid >> 5, lane = tid & 31;
    const int c0 = lane, c1 = lane + 32;
    const float b1_0 = sB1[c0], b1_1 = sB1[c1];
    const float b2_0 = sB2[c0], b2_1 = sB2[c1];
    const float g0 = sG[c0], g1 = sG[c1];
    const float bb0 = sB[c0], bb1 = sB[c1];
    float* myIn = sIn + warp * 1024;
    float* myT  = sT + warp * 512;

    const int gw = blockIdx.x * WARPS + warp;
    const int nwarps = gridDim.x * WARPS;

    for (int base = gw * EPT; base < NN; base += nwarps * EPT) {
#pragma unroll
        for (int e = 0; e < EPT; e++) {
            const float* mip = g_mi + (size_t)(base + e) * H;
            const float* hp  = h + (size_t)(base + e) * H;
            *reinterpret_cast<float2*>(myIn + e * 128 + 2 * lane) =
                *reinterpret_cast<const float2*>(mip + 2 * lane);
            *reinterpret_cast<float2*>(myIn + e * 128 + 64 + 2 * lane) =
                *reinterpret_cast<const float2*>(hp + 2 * lane);
        }
        __syncwarp();

        float a0[EPT], a1[EPT];
#pragma unroll
        for (int e = 0; e < EPT; e++) { a0[e] = b1_0; a1[e] = b1_1; }
#pragma unroll 2
        for (int k = 0; k < 128; k += 4) {
            float4 w0 = *reinterpret_cast<const float4*>(sW1 + c0 * 132 + k);
            float4 w1 = *reinterpret_cast<const float4*>(sW1 + c1 * 132 + k);
#pragma unroll
            for (int e = 0; e < EPT; e++) {
                float4 v = *reinterpret_cast<const float4*>(myIn + e * 128 + k);
                a0[e] = fmaf(v.x, w0.x, a0[e]); a0[e] = fmaf(v.y, w0.y, a0[e]);
                a0[e] = fmaf(v.z, w0.z, a0[e]); a0[e] = fmaf(v.w, w0.w, a0[e]);
                a1[e] = fmaf(v.x, w1.x, a1[e]); a1[e] = fmaf(v.y, w1.y, a1[e]);
                a1[e] = fmaf(v.z, w1.z, a1[e]); a1[e] = fmaf(v.w, w1.w, a1[e]);
            }
        }
#pragma unroll
        for (int e = 0; e < EPT; e++) {
            myT[e * 64 + c0] = fmaxf(a0[e], 0.0f);
            myT[e * 64 + c1] = fmaxf(a1[e], 0.0f);
        }
        __syncwarp();

        float u0[EPT], u1[EPT];
#pragma unroll
        for (int e = 0; e < EPT; e++) { u0[e] = b2_0; u1[e] = b2_1; }
#pragma unroll 2
        for (int k = 0; k < 64; k += 4) {
            float4 w0 = *reinterpret_cast<const float4*>(sW2 + c0 * 68 + k);
            float4 w1 = *reinterpret_cast<const float4*>(sW2 + c1 * 68 + k);
#pragma unroll
            for (int e = 0; e < EPT; e++) {
                float4 v = *reinterpret_cast<const float4*>(myT + e * 64 + k);
                u0[e] = fmaf(v.x, w0.x, u0[e]); u0[e] = fmaf(v.y, w0.y, u0[e]);
                u0[e] = fmaf(v.z, w0.z, u0[e]); u0[e] = fmaf(v.w, w0.w, u0[e]);
                u1[e] = fmaf(v.x, w1.x, u1[e]); u1[e] = fmaf(v.y, w1.y, u1[e]);
                u1[e] = fmaf(v.z, w1.z, u1[e]); u1[e] = fmaf(v.w, w1.w, u1[e]);
            }
        }

#pragma unroll
        for (int e = 0; e < EPT; e++) {
            float z0 = u0[e] + myIn[e * 128 + 64 + c0];
            float z1 = u1[e] + myIn[e * 128 + 64 + c1];
            float s = z0 + z1;
            float q = z0 * z0 + z1 * z1;
#pragma unroll
            for (int o = 16; o > 0; o >>= 1) {
                s += __shfl_xor_sync(0xffffffffu, s, o);
                q += __shfl_xor_sync(0xffffffffu, q, o);
            }
            float mean = s * (1.0f / 64.0f);
            float var = q * (1.0f / 64.0f) - mean * mean;
            float inv = rsqrtf(var + 1e-5f);
            size_t ro = (size_t)(base + e) * H;
            out[ro + c0] = (z0 - mean) * inv * g0 + bb0;
            out[ro + c1] = (z1 - mean) * inv * g1 + bb1;
        }
        __syncwarp();
    }
}

__global__ void copy_x_kernel(const float4* __restrict__ x, float4* __restrict__ out)
{
    int i = blockIdx.x * blockDim.x + threadIdx.x;
    if (i < (NN * 3) / 4) out[i] = x[i];
}

extern "C" void kernel_launch(void* const* d_in, const int* in_sizes, int n_in,
                              void* d_out, int out_size)
{
    const float* h    = (const float*)d_in[0];
    const float* x    = (const float*)d_in[1];
    const int*   ei   = (const int*)d_in[2];
    const float* We1  = (const float*)d_in[3];
    const float* be1  = (const float*)d_in[4];
    const float* We2  = (const float*)d_in[5];
    const float* be2  = (const float*)d_in[6];
    const float* Winf = (const float*)d_in[7];
    const float* binf = (const float*)d_in[8];
    const float* Wn1  = (const float*)d_in[9];
    const float* bn1  = (const float*)d_in[10];
    const float* Wn2  = (const float*)d_in[11];
    const float* bn2  = (const float*)d_in[12];
    const float* lng  = (const float*)d_in[13];
    const float* lnb  = (const float*)d_in[14];
    float* out = (float*)d_out;

    void* mi_ptr = nullptr;
    cudaGetSymbolAddress(&mi_ptr, g_mi);
    cudaMemsetAsync(mi_ptr, 0, sizeof(float) * (size_t)NN * H, 0);
    precompute_kernel<<<(NN + 63) / 64, 256>>>(h, We1);

    cudaFuncSetAttribute(edge_mma_kernel, cudaFuncAttributeMaxDynamicSharedMemorySize, EK_SMEM_BYTES);
    cudaFuncSetAttribute(node_kernel, cudaFuncAttributeMaxDynamicSharedMemorySize, NK_SMEM_BYTES);

    edge_mma_kernel<<<296, 256, EK_SMEM_BYTES>>>(x, ei, be1, We2, be2, Winf, binf);
    node_kernel<<<296, 256, NK_SMEM_BYTES>>>(h, Wn1, bn1, Wn2, bn2, lng, lnb, out);

    if (out_size >= NN * H + NN * 3) {
        copy_x_kernel<<<(NN * 3 / 4 + 255) / 256, 256>>>((const float4*)x,
                                                         (float4*)(out + (size_t)NN * H));
    }
}